// round 1
// baseline (speedup 1.0000x reference)
#include <cuda_runtime.h>
#include <cuda_bf16.h>
#include <math.h>

// Problem constants
#define BB 16
#define PP 512
#define DD 1024
#define WW 400
#define TT 32
#define EE 64
#define HH 600
#define NPAIR (TT * EE)   // 2048

// ---------------- scratch (static device globals; no runtime alloc) -------
__device__ float g_word[(size_t)BB * WW * DD];   // 26.2 MB
__device__ float g_trig[(size_t)BB * TT * DD];   // 2 MB
__device__ float g_ent [(size_t)BB * EE * DD];   // 4 MB
__device__ float g_Pt  [(size_t)BB * TT * HH];   // 1.2 MB  (includes b0)
__device__ float g_Pe  [(size_t)BB * EE * HH];   // 2.5 MB
__device__ float g_h   [(size_t)BB * NPAIR * HH];// 78.6 MB (post-relu hidden)

// ---------------- kernel 1: wordpiece -> word mean -------------------------
// grid (WW, BB), block 256 (4 cols each via float4)
__global__ void word_mean_kernel(const float* __restrict__ piece,
                                 const int* __restrict__ widx,
                                 float* __restrict__ out) {
    int w = blockIdx.x, b = blockIdx.y;
    int s = widx[(b * WW + w) * 2];
    int e = widx[(b * WW + w) * 2 + 1];
    float inv = 1.0f / (float)(e - s);
    const float* base = piece + (size_t)b * PP * DD;
    int t = threadIdx.x;  // 0..255, handles cols 4t..4t+3
    float a0 = 0.f, a1 = 0.f, a2 = 0.f, a3 = 0.f;
    for (int r = s; r < e; r++) {
        float4 v = ((const float4*)(base + (size_t)r * DD))[t];
        a0 += v.x; a1 += v.y; a2 += v.z; a3 += v.w;
    }
    float4 o = make_float4(a0 * inv, a1 * inv, a2 * inv, a3 * inv);
    ((float4*)(out + (size_t)(b * WW + w) * DD))[t] = o;
}

// ---------------- kernel 2: word -> span mean -------------------------------
// grid (M, BB), block 256
__global__ void span_mean_kernel(const float* __restrict__ words,
                                 const int* __restrict__ idx,
                                 float* __restrict__ out, int M) {
    int m = blockIdx.x, b = blockIdx.y;
    int s = idx[(b * M + m) * 2];
    int e = idx[(b * M + m) * 2 + 1];
    float inv = 1.0f / (float)(e - s);
    const float* base = words + (size_t)b * WW * DD;
    int t = threadIdx.x;
    float a0 = 0.f, a1 = 0.f, a2 = 0.f, a3 = 0.f;
    for (int r = s; r < e; r++) {
        float4 v = ((const float4*)(base + (size_t)r * DD))[t];
        a0 += v.x; a1 += v.y; a2 += v.z; a3 += v.w;
    }
    float4 o = make_float4(a0 * inv, a1 * inv, a2 * inv, a3 * inv);
    ((float4*)(out + (size_t)(b * M + m) * DD))[t] = o;
}

// ---------------- kernel 3: generic tiled GEMM C = A@B (+bias) -------------
// A:[M,K] row-major, B:[K,N] row-major, C:[M,N]. Tile 64x64, block (16,16),
// thread tile 4x4 (strided mapping). M multiple of 64, K multiple of 16.
__global__ void gemm_bias_kernel(const float* __restrict__ A,
                                 const float* __restrict__ B,
                                 const float* __restrict__ bias,
                                 float* __restrict__ C,
                                 int M, int N, int K) {
    __shared__ float As[16][64];
    __shared__ float Bs[16][64];
    int tx = threadIdx.x, ty = threadIdx.y;
    int tid = ty * 16 + tx;
    int m0 = blockIdx.y * 64, n0 = blockIdx.x * 64;

    float acc[4][4];
#pragma unroll
    for (int i = 0; i < 4; i++)
#pragma unroll
        for (int j = 0; j < 4; j++) acc[i][j] = 0.f;

    int rowA = tid >> 2, kqA = (tid & 3) * 4;     // A loader: 64 rows x 16 k
    int kB = tid >> 4, n4 = (tid & 15) * 4;       // B loader: 16 k x 64 n

    for (int k0 = 0; k0 < K; k0 += 16) {
        float4 av = *(const float4*)(A + (size_t)(m0 + rowA) * K + k0 + kqA);
        As[kqA + 0][rowA] = av.x;
        As[kqA + 1][rowA] = av.y;
        As[kqA + 2][rowA] = av.z;
        As[kqA + 3][rowA] = av.w;
        float4 bv = make_float4(0.f, 0.f, 0.f, 0.f);
        if (n0 + n4 < N)
            bv = *(const float4*)(B + (size_t)(k0 + kB) * N + n0 + n4);
        Bs[kB][n4 + 0] = bv.x;
        Bs[kB][n4 + 1] = bv.y;
        Bs[kB][n4 + 2] = bv.z;
        Bs[kB][n4 + 3] = bv.w;
        __syncthreads();
#pragma unroll
        for (int k = 0; k < 16; k++) {
            float a[4], bb[4];
#pragma unroll
            for (int i = 0; i < 4; i++) a[i] = As[k][ty + 16 * i];
#pragma unroll
            for (int j = 0; j < 4; j++) bb[j] = Bs[k][tx + 16 * j];
#pragma unroll
            for (int i = 0; i < 4; i++)
#pragma unroll
                for (int j = 0; j < 4; j++) acc[i][j] = fmaf(a[i], bb[j], acc[i][j]);
        }
        __syncthreads();
    }
#pragma unroll
    for (int i = 0; i < 4; i++) {
        int m = m0 + ty + 16 * i;
        if (m >= M) continue;
#pragma unroll
        for (int j = 0; j < 4; j++) {
            int n = n0 + tx + 16 * j;
            if (n < N) {
                float v = acc[i][j];
                if (bias) v += bias[n];
                C[(size_t)m * N + n] = v;
            }
        }
    }
}

// ---------------- kernel 4: fused pair GEMM -> relu hidden ------------------
// grid (5 h-tiles of 128, TT, BB), block (16,16). Per block: 64 e-rows x 128 h.
// A-tile generated on the fly: phase0 = trig*ent (W0 rows [2D,3D)),
// phase1 = |trig-ent| (W0 rows [3D,4D)). Epilogue adds Pt (incl b0) + Pe, relu.
__global__ __launch_bounds__(256) void pair_gemm_kernel(
    const float* __restrict__ trig, const float* __restrict__ ent,
    const float* __restrict__ W0,
    const float* __restrict__ Pt, const float* __restrict__ Pe,
    float* __restrict__ Hout) {
    int htile = blockIdx.x;       // 0..4 -> n0 = htile*128
    int t = blockIdx.y;           // trigger
    int b = blockIdx.z;           // batch
    int n0 = htile * 128;

    __shared__ float trig_s[DD];
    __shared__ float As[16][64];
    __shared__ float Bs[16][128];

    int tx = threadIdx.x, ty = threadIdx.y;
    int tid = ty * 16 + tx;

    // load full trigger row into smem
    {
        const float4* src = (const float4*)(trig + (size_t)(b * TT + t) * DD);
        ((float4*)trig_s)[tid] = src[tid];
    }
    __syncthreads();

    float acc[4][8];
#pragma unroll
    for (int i = 0; i < 4; i++)
#pragma unroll
        for (int j = 0; j < 8; j++) acc[i][j] = 0.f;

    int rowA = tid >> 2, kqA = (tid & 3) * 4;   // ent loader: 64 rows x 16 k
    int kB = tid >> 4, n8 = (tid & 15) * 8;     // W0 loader: 16 k x 128 n (2x float4)

    const float* entb = ent + (size_t)b * EE * DD;

#pragma unroll 1
    for (int phase = 0; phase < 2; phase++) {
        const float* W0base = W0 + (size_t)(2 * DD + phase * DD) * HH;
#pragma unroll 1
        for (int k0 = 0; k0 < DD; k0 += 16) {
            // generate A chunk
            float4 ev = *(const float4*)(entb + (size_t)rowA * DD + k0 + kqA);
            if (phase == 0) {
                As[kqA + 0][rowA] = trig_s[k0 + kqA + 0] * ev.x;
                As[kqA + 1][rowA] = trig_s[k0 + kqA + 1] * ev.y;
                As[kqA + 2][rowA] = trig_s[k0 + kqA + 2] * ev.z;
                As[kqA + 3][rowA] = trig_s[k0 + kqA + 3] * ev.w;
            } else {
                As[kqA + 0][rowA] = fabsf(trig_s[k0 + kqA + 0] - ev.x);
                As[kqA + 1][rowA] = fabsf(trig_s[k0 + kqA + 1] - ev.y);
                As[kqA + 2][rowA] = fabsf(trig_s[k0 + kqA + 2] - ev.z);
                As[kqA + 3][rowA] = fabsf(trig_s[k0 + kqA + 3] - ev.w);
            }
            // load W0 chunk (guard h >= 600)
#pragma unroll
            for (int half = 0; half < 2; half++) {
                int n = n8 + half * 4;
                float4 bv = make_float4(0.f, 0.f, 0.f, 0.f);
                if (n0 + n < HH)
                    bv = *(const float4*)(W0base + (size_t)(k0 + kB) * HH + n0 + n);
                Bs[kB][n + 0] = bv.x;
                Bs[kB][n + 1] = bv.y;
                Bs[kB][n + 2] = bv.z;
                Bs[kB][n + 3] = bv.w;
            }
            __syncthreads();
#pragma unroll
            for (int k = 0; k < 16; k++) {
                float a[4], bb[8];
#pragma unroll
                for (int i = 0; i < 4; i++) a[i] = As[k][ty + 16 * i];
#pragma unroll
                for (int j = 0; j < 8; j++) bb[j] = Bs[k][tx + 16 * j];
#pragma unroll
                for (int i = 0; i < 4; i++)
#pragma unroll
                    for (int j = 0; j < 8; j++) acc[i][j] = fmaf(a[i], bb[j], acc[i][j]);
            }
            __syncthreads();
        }
    }

    // epilogue: + Pt(t,h) + Pe(e,h), relu, store to g_h
    const float* ptRow = Pt + (size_t)(b * TT + t) * HH;
#pragma unroll
    for (int j = 0; j < 8; j++) {
        int hc = n0 + tx + 16 * j;
        if (hc >= HH) continue;
        float ptv = ptRow[hc];
#pragma unroll
        for (int i = 0; i < 4; i++) {
            int e = ty + 16 * i;
            float v = acc[i][j] + ptv + Pe[(size_t)(b * EE + e) * HH + hc];
            v = fmaxf(v, 0.f);
            int p = t * EE + e;
            Hout[((size_t)b * NPAIR + p) * HH + hc] = v;
        }
    }
}

// ---------------- kernel 5: layer 2 (600 -> 2) ------------------------------
// one warp per row; block 256 = 8 rows.
__global__ void layer2_kernel(const float* __restrict__ Hbuf,
                              const float* __restrict__ W1,
                              const float* __restrict__ b1,
                              float* __restrict__ out) {
    int warp = threadIdx.x >> 5;
    int lane = threadIdx.x & 31;
    size_t row = (size_t)blockIdx.x * 8 + warp;  // < 16*2048
    const float* hrow = Hbuf + row * HH;
    float a0 = 0.f, a1 = 0.f;
    for (int h = lane; h < HH; h += 32) {
        float v = hrow[h];
        a0 = fmaf(v, W1[h * 2 + 0], a0);
        a1 = fmaf(v, W1[h * 2 + 1], a1);
    }
#pragma unroll
    for (int off = 16; off > 0; off >>= 1) {
        a0 += __shfl_down_sync(0xffffffffu, a0, off);
        a1 += __shfl_down_sync(0xffffffffu, a1, off);
    }
    if (lane == 0) {
        out[row * 2 + 0] = a0 + b1[0];
        out[row * 2 + 1] = a1 + b1[1];
    }
}

// ---------------- launch ----------------------------------------------------
extern "C" void kernel_launch(void* const* d_in, const int* in_sizes, int n_in,
                              void* d_out, int out_size) {
    const float* piece = (const float*)d_in[0];
    const int*   widx  = (const int*)d_in[1];
    const int*   tidx  = (const int*)d_in[2];
    const int*   eidx  = (const int*)d_in[3];
    const float* W0    = (const float*)d_in[4];
    const float* b0    = (const float*)d_in[5];
    const float* W1    = (const float*)d_in[6];
    const float* b1    = (const float*)d_in[7];
    float* out = (float*)d_out;

    float *wordp, *trigp, *entp, *Ptp, *Pep, *hp;
    cudaGetSymbolAddress((void**)&wordp, g_word);
    cudaGetSymbolAddress((void**)&trigp, g_trig);
    cudaGetSymbolAddress((void**)&entp,  g_ent);
    cudaGetSymbolAddress((void**)&Ptp,   g_Pt);
    cudaGetSymbolAddress((void**)&Pep,   g_Pe);
    cudaGetSymbolAddress((void**)&hp,    g_h);

    // 1) word means
    word_mean_kernel<<<dim3(WW, BB), 256>>>(piece, widx, wordp);
    // 2) span means
    span_mean_kernel<<<dim3(TT, BB), 256>>>(wordp, tidx, trigp, TT);
    span_mean_kernel<<<dim3(EE, BB), 256>>>(wordp, eidx, entp, EE);
    // 3) Pt = trig @ W0[0:D] + b0 ; Pe = ent @ W0[D:2D]
    gemm_bias_kernel<<<dim3((HH + 63) / 64, (BB * TT) / 64), dim3(16, 16)>>>(
        trigp, W0, b0, Ptp, BB * TT, HH, DD);
    gemm_bias_kernel<<<dim3((HH + 63) / 64, (BB * EE) / 64), dim3(16, 16)>>>(
        entp, W0 + (size_t)DD * HH, nullptr, Pep, BB * EE, HH, DD);
    // 4) fused pair GEMM -> relu hidden
    pair_gemm_kernel<<<dim3(5, TT, BB), dim3(16, 16)>>>(
        trigp, entp, W0, Ptp, Pep, hp);
    // 5) layer 2
    layer2_kernel<<<(BB * NPAIR) / 8, 256>>>(hp, W1, b1, out);
    (void)in_sizes; (void)n_in; (void)out_size;
}

// round 5
// speedup vs baseline: 2.2112x; 2.2112x over previous
#include <cuda_runtime.h>
#include <cuda_fp16.h>
#include <math.h>
#include <stdint.h>

// Problem constants
#define BB 16
#define PP 512
#define DD 1024
#define WW 400
#define TT 32
#define EE 64
#define HH 600
#define NPAIR (TT * EE)     // 2048
#define KF 4096             // role feature length [t | e | t*e | |t-e|]
#define NPAD 640
#define KC 64               // k per chunk
#define NCHUNK (KF / KC)    // 64
#define NTILES 5            // h tiles of 128

// smem geometry (bytes): A[128 rows][64 halves] pitch 144, B same shape
#define PITCH 144
#define A_BYTES (128 * PITCH)             // 18432
#define B_OFF   A_BYTES
#define STAGE_BYTES (2 * A_BYTES)         // 36864
#define SMEM_DYN (2 * STAGE_BYTES)        // 73728

// ---------------- scratch ----------------------------------------------------
__device__ float g_word[(size_t)BB * WW * DD];
__device__ float g_trig[(size_t)BB * TT * DD];
__device__ float g_ent [(size_t)BB * EE * DD];
__device__ __half g_W0T[(size_t)NPAD * KF];          // W0 transposed fp16 [n][k]
__device__ float g_part[(size_t)NTILES * BB * NPAIR * 2];

// ---------------- helpers ----------------------------------------------------
__device__ __forceinline__ void mma16816(float* c, const uint32_t* a, const uint32_t* b) {
    asm volatile(
        "mma.sync.aligned.m16n8k16.row.col.f32.f16.f16.f32 "
        "{%0,%1,%2,%3}, {%4,%5,%6,%7}, {%8,%9}, {%0,%1,%2,%3};"
        : "+f"(c[0]), "+f"(c[1]), "+f"(c[2]), "+f"(c[3])
        : "r"(a[0]), "r"(a[1]), "r"(a[2]), "r"(a[3]), "r"(b[0]), "r"(b[1]));
}
__device__ __forceinline__ void cp16(uint32_t dst, const void* src) {
    asm volatile("cp.async.ca.shared.global [%0], [%1], 16;" :: "r"(dst), "l"(src) : "memory");
}
__device__ __forceinline__ uint32_t smem_u32(const void* p) {
    uint32_t a;
    asm("{ .reg .u64 t; cvta.to.shared.u64 t, %1; cvt.u32.u64 %0, t; }"
        : "=r"(a) : "l"(p));
    return a;
}
__device__ __forceinline__ uint32_t pack_h2(float lo, float hi) {
    uint32_t r;
    asm("cvt.rn.f16x2.f32 %0, %1, %2;" : "=r"(r) : "f"(hi), "f"(lo));  // first src -> high
    return r;
}

// ---------------- kernel 1: wordpiece -> word mean ---------------------------
__global__ void word_mean_kernel(const float* __restrict__ piece,
                                 const int* __restrict__ widx,
                                 float* __restrict__ out) {
    int w = blockIdx.x, b = blockIdx.y;
    int s = widx[(b * WW + w) * 2];
    int e = widx[(b * WW + w) * 2 + 1];
    float inv = 1.0f / (float)(e - s);
    const float* base = piece + (size_t)b * PP * DD;
    int t = threadIdx.x;
    float a0 = 0.f, a1 = 0.f, a2 = 0.f, a3 = 0.f;
    for (int r = s; r < e; r++) {
        float4 v = ((const float4*)(base + (size_t)r * DD))[t];
        a0 += v.x; a1 += v.y; a2 += v.z; a3 += v.w;
    }
    float4 o = make_float4(a0 * inv, a1 * inv, a2 * inv, a3 * inv);
    ((float4*)(out + (size_t)(b * WW + w) * DD))[t] = o;
}

// ---------------- kernel 2: word -> span mean --------------------------------
__global__ void span_mean_kernel(const float* __restrict__ words,
                                 const int* __restrict__ idx,
                                 float* __restrict__ out, int M) {
    int m = blockIdx.x, b = blockIdx.y;
    int s = idx[(b * M + m) * 2];
    int e = idx[(b * M + m) * 2 + 1];
    float inv = 1.0f / (float)(e - s);
    const float* base = words + (size_t)b * WW * DD;
    int t = threadIdx.x;
    float a0 = 0.f, a1 = 0.f, a2 = 0.f, a3 = 0.f;
    for (int r = s; r < e; r++) {
        float4 v = ((const float4*)(base + (size_t)r * DD))[t];
        a0 += v.x; a1 += v.y; a2 += v.z; a3 += v.w;
    }
    float4 o = make_float4(a0 * inv, a1 * inv, a2 * inv, a3 * inv);
    ((float4*)(out + (size_t)(b * M + m) * DD))[t] = o;
}

// ---------------- kernel 3: W0 [k][HH] -> W0T fp16 [NPAD][KF] ----------------
__global__ void bprep_kernel(const float* __restrict__ W0,
                             __half* __restrict__ W0T) {
    __shared__ float tile[32][33];
    int k0 = blockIdx.x * 32, n0 = blockIdx.y * 32;
    int x = threadIdx.x, y = threadIdx.y;
    float v = 0.f;
    if (n0 + x < HH) v = W0[(size_t)(k0 + y) * HH + (n0 + x)];
    tile[y][x] = v;
    __syncthreads();
    float w = tile[x][y];  // = W0[k0+x][n0+y]
    W0T[(size_t)(n0 + y) * KF + (k0 + x)] = __float2half_rn(w);
}

// ---------------- kernel 4: fused pair GEMM (mma.sync, explicit LDS frags) ---
// grid (NTILES, TT/2, BB), block 256 (8 warps, warp grid 2x4).
// Block tile: M=128 pair rows (2 trig x 64 ent) x N=128 h cols, K=4096 feats.
// A generated on the fly; B = W0T slice. fp32 accum. Epilogue fuses +b0, relu,
// @W1 -> per-ntile output partials.
__global__ __launch_bounds__(256)
void pair_mma_kernel(const float* __restrict__ trig,
                     const float* __restrict__ ent,
                     const __half* __restrict__ W0T,
                     const float* __restrict__ b0,
                     const float* __restrict__ W1,
                     float* __restrict__ part) {
    extern __shared__ char dsm[];
    __shared__ float trig_s[2 * DD];
    __shared__ float red[128][4][2];

    uint32_t sb = smem_u32(dsm);
    int tid = threadIdx.x;
    int lane = tid & 31, warp = tid >> 5;
    int wm = warp >> 2, wn = warp & 3;
    int g = lane >> 2, t2 = (lane & 3) * 2;
    int nt = blockIdx.x, mt = blockIdx.y, b = blockIdx.z;
    int n0 = nt * 128;

    // load 2 trigger rows into smem
    {
        const float4* src = (const float4*)(trig + (size_t)(b * TT + 2 * mt) * DD);
        ((float4*)trig_s)[tid]       = src[tid];
        ((float4*)trig_s)[tid + 256] = src[tid + 256];
    }

    // ---- producer roles: row = tid>>1 (0..127), half cb = (tid&1)*32
    int prow = tid >> 1;
    int cb = (tid & 1) * 32;
    int tl = prow >> 6, ei = prow & 63;
    const float* trow = trig_s + tl * DD;
    const float* erow = ent + (size_t)(b * EE + ei) * DD;
    uint32_t aDst = sb + (uint32_t)prow * PITCH + cb * 2;
    uint32_t bDst = sb + B_OFF + (uint32_t)prow * PITCH + cb * 2;
    const __half* bSrcBase = W0T + (size_t)(n0 + prow) * KF + cb;

    // ---- consumer fragment base offsets (PTX ISA m16n8k16 layouts)
    uint32_t aLd = sb + (uint32_t)(wm * 64 + g) * PITCH + (uint32_t)t2 * 2;
    uint32_t bLd = sb + B_OFF + (uint32_t)(wn * 32 + g) * PITCH + (uint32_t)t2 * 2;

    float acc[4][4][4];
#pragma unroll
    for (int i = 0; i < 4; i++)
#pragma unroll
        for (int j = 0; j < 4; j++)
#pragma unroll
            for (int q = 0; q < 4; q++) acc[i][j][q] = 0.f;

    __syncthreads();   // trig_s ready

    // ---- prologue: produce chunk 0 into stage 0
    {
        float va[32];
#pragma unroll
        for (int j = 0; j < 32; j++) va[j] = trow[cb + j];
#pragma unroll
        for (int gq = 0; gq < 4; gq++) {
            uint32_t p0 = pack_h2(va[gq*8+0], va[gq*8+1]);
            uint32_t p1 = pack_h2(va[gq*8+2], va[gq*8+3]);
            uint32_t p2 = pack_h2(va[gq*8+4], va[gq*8+5]);
            uint32_t p3 = pack_h2(va[gq*8+6], va[gq*8+7]);
            asm volatile("st.shared.v4.b32 [%0], {%1,%2,%3,%4};"
                         :: "r"(aDst + gq * 16), "r"(p0), "r"(p1), "r"(p2), "r"(p3) : "memory");
        }
#pragma unroll
        for (int q = 0; q < 4; q++)
            cp16(bDst + q * 16, (const char*)bSrcBase + q * 16);
        asm volatile("cp.async.wait_all;" ::: "memory");
    }
    __syncthreads();

    // ---- main loop over 64 chunks
    for (int c = 0; c < NCHUNK; c++) {
        uint32_t stageOff = (uint32_t)(c & 1) * STAGE_BYTES;
        int cn = c + 1;
        int blkN = cn >> 4, kkN = (cn & 15) * KC;
        uint32_t nStage = (uint32_t)(cn & 1) * STAGE_BYTES;
        float ev[32];

        // P1: prefetch next-chunk gmem (ent row regs + B cp.async)
        if (cn < NCHUNK) {
            if (blkN != 0) {
#pragma unroll
                for (int q = 0; q < 8; q++) {
                    float4 v = ((const float4*)(erow + kkN + cb))[q];
                    ev[q*4+0] = v.x; ev[q*4+1] = v.y; ev[q*4+2] = v.z; ev[q*4+3] = v.w;
                }
            }
            const char* bs = (const char*)(bSrcBase + cn * KC);
#pragma unroll
            for (int q = 0; q < 4; q++)
                cp16(bDst + nStage + q * 16, bs + q * 16);
        }

        // MMA: 4 k-steps of 16 over current stage
#pragma unroll
        for (int ks = 0; ks < 4; ks++) {
            uint32_t afr[4][4], bfr[4][2];
            uint32_t aO = aLd + stageOff + (uint32_t)ks * 32;
            uint32_t bO = bLd + stageOff + (uint32_t)ks * 32;
#pragma unroll
            for (int j = 0; j < 4; j++) {
                uint32_t o = bO + (uint32_t)j * (8 * PITCH);
                asm volatile("ld.shared.b32 %0, [%1];" : "=r"(bfr[j][0]) : "r"(o));
                asm volatile("ld.shared.b32 %0, [%1];" : "=r"(bfr[j][1]) : "r"(o + 16));
            }
#pragma unroll
            for (int i = 0; i < 4; i++) {
                uint32_t o = aO + (uint32_t)i * (16 * PITCH);
                asm volatile("ld.shared.b32 %0, [%1];" : "=r"(afr[i][0]) : "r"(o));
                asm volatile("ld.shared.b32 %0, [%1];" : "=r"(afr[i][1]) : "r"(o + 8 * PITCH));
                asm volatile("ld.shared.b32 %0, [%1];" : "=r"(afr[i][2]) : "r"(o + 16));
                asm volatile("ld.shared.b32 %0, [%1];" : "=r"(afr[i][3]) : "r"(o + 8 * PITCH + 16));
            }
#pragma unroll
            for (int i = 0; i < 4; i++)
#pragma unroll
                for (int j = 0; j < 4; j++)
                    mma16816(acc[i][j], afr[i], bfr[j]);
        }

        // P2: convert + store next-chunk A  (ALL four feature blocks handled)
        if (cn < NCHUNK) {
            float va[32];
            if (blkN == 0) {
#pragma unroll
                for (int j = 0; j < 32; j++) va[j] = trow[kkN + cb + j];
            } else if (blkN == 1) {
#pragma unroll
                for (int j = 0; j < 32; j++) va[j] = ev[j];
            } else if (blkN == 2) {
#pragma unroll
                for (int j = 0; j < 32; j++) va[j] = trow[kkN + cb + j] * ev[j];
            } else {
#pragma unroll
                for (int j = 0; j < 32; j++) va[j] = fabsf(trow[kkN + cb + j] - ev[j]);
            }
            uint32_t dst = aDst + nStage;
#pragma unroll
            for (int gq = 0; gq < 4; gq++) {
                uint32_t p0 = pack_h2(va[gq*8+0], va[gq*8+1]);
                uint32_t p1 = pack_h2(va[gq*8+2], va[gq*8+3]);
                uint32_t p2 = pack_h2(va[gq*8+4], va[gq*8+5]);
                uint32_t p3 = pack_h2(va[gq*8+6], va[gq*8+7]);
                asm volatile("st.shared.v4.b32 [%0], {%1,%2,%3,%4};"
                             :: "r"(dst + gq * 16), "r"(p0), "r"(p1), "r"(p2), "r"(p3) : "memory");
            }
            asm volatile("cp.async.wait_all;" ::: "memory");
        }
        __syncthreads();
    }

    // ---- epilogue: +b0, relu, contract with W1 -> per-row partials
    float pr[4][2][2];
#pragma unroll
    for (int i = 0; i < 4; i++)
#pragma unroll
        for (int hh = 0; hh < 2; hh++) { pr[i][hh][0] = 0.f; pr[i][hh][1] = 0.f; }

#pragma unroll
    for (int j = 0; j < 4; j++) {
        int hcol = n0 + wn * 32 + j * 8 + t2;
#pragma unroll
        for (int cp = 0; cp < 2; cp++) {
            int h = hcol + cp;
            if (h < HH) {
                float bb = b0[h];
                float w10 = W1[2 * h], w11 = W1[2 * h + 1];
#pragma unroll
                for (int i = 0; i < 4; i++) {
                    float v0 = fmaxf(acc[i][j][cp] + bb, 0.f);       // row g
                    float v1 = fmaxf(acc[i][j][2 + cp] + bb, 0.f);   // row g+8
                    pr[i][0][0] = fmaf(v0, w10, pr[i][0][0]);
                    pr[i][0][1] = fmaf(v0, w11, pr[i][0][1]);
                    pr[i][1][0] = fmaf(v1, w10, pr[i][1][0]);
                    pr[i][1][1] = fmaf(v1, w11, pr[i][1][1]);
                }
            }
        }
    }
#pragma unroll
    for (int i = 0; i < 4; i++)
#pragma unroll
        for (int hh = 0; hh < 2; hh++)
#pragma unroll
            for (int o = 0; o < 2; o++) {
                float v = pr[i][hh][o];
                v += __shfl_xor_sync(0xffffffffu, v, 1);
                v += __shfl_xor_sync(0xffffffffu, v, 2);
                pr[i][hh][o] = v;
            }
    if ((lane & 3) == 0) {
#pragma unroll
        for (int i = 0; i < 4; i++)
#pragma unroll
            for (int hh = 0; hh < 2; hh++) {
                int row = wm * 64 + i * 16 + g + hh * 8;
                red[row][wn][0] = pr[i][hh][0];
                red[row][wn][1] = pr[i][hh][1];
            }
    }
    __syncthreads();
    if (tid < 128) {
        int row = tid;
        float a0 = 0.f, a1 = 0.f;
#pragma unroll
        for (int wc = 0; wc < 4; wc++) {
            a0 += red[row][wc][0];
            a1 += red[row][wc][1];
        }
        int pair = (2 * mt + (row >> 6)) * EE + (row & 63);
        size_t oidx = ((size_t)nt * BB * NPAIR + (size_t)b * NPAIR + pair) * 2;
        part[oidx]     = a0;
        part[oidx + 1] = a1;
    }
}

// ---------------- kernel 5: reduce 5 partials + b1 ---------------------------
__global__ void reduce_out_kernel(const float* __restrict__ part,
                                  const float* __restrict__ b1,
                                  float* __restrict__ out) {
    int i = blockIdx.x * blockDim.x + threadIdx.x;
    float a = b1[i & 1];
#pragma unroll
    for (int t = 0; t < NTILES; t++)
        a += part[(size_t)t * BB * NPAIR * 2 + i];
    out[i] = a;
}

// ---------------- launch -----------------------------------------------------
extern "C" void kernel_launch(void* const* d_in, const int* in_sizes, int n_in,
                              void* d_out, int out_size) {
    const float* piece = (const float*)d_in[0];
    const int*   widx  = (const int*)d_in[1];
    const int*   tidx  = (const int*)d_in[2];
    const int*   eidx  = (const int*)d_in[3];
    const float* W0    = (const float*)d_in[4];
    const float* b0    = (const float*)d_in[5];
    const float* W1    = (const float*)d_in[6];
    const float* b1    = (const float*)d_in[7];
    float* out = (float*)d_out;

    float *wordp, *trigp, *entp, *partp;
    __half* w0tp;
    cudaGetSymbolAddress((void**)&wordp, g_word);
    cudaGetSymbolAddress((void**)&trigp, g_trig);
    cudaGetSymbolAddress((void**)&entp,  g_ent);
    cudaGetSymbolAddress((void**)&w0tp,  g_W0T);
    cudaGetSymbolAddress((void**)&partp, g_part);

    cudaFuncSetAttribute(pair_mma_kernel,
                         cudaFuncAttributeMaxDynamicSharedMemorySize, SMEM_DYN);

    word_mean_kernel<<<dim3(WW, BB), 256>>>(piece, widx, wordp);
    span_mean_kernel<<<dim3(TT, BB), 256>>>(wordp, tidx, trigp, TT);
    span_mean_kernel<<<dim3(EE, BB), 256>>>(wordp, eidx, entp, EE);
    bprep_kernel<<<dim3(KF / 32, NPAD / 32), dim3(32, 32)>>>(W0, w0tp);
    pair_mma_kernel<<<dim3(NTILES, TT / 2, BB), 256, SMEM_DYN>>>(
        trigp, entp, w0tp, b0, W1, partp);
    reduce_out_kernel<<<(BB * NPAIR * 2) / 1024, 1024>>>(partp, b1, out);
    (void)in_sizes; (void)n_in; (void)out_size;
}

// round 6
// speedup vs baseline: 3.3021x; 1.4934x over previous
#include <cuda_runtime.h>
#include <cuda_fp16.h>
#include <math.h>
#include <stdint.h>

// Problem constants
#define BB 16
#define PP 512
#define DD 1024
#define WW 400
#define TT 32
#define EE 64
#define HH 600
#define NPAIR (TT * EE)     // 2048
#define KF 4096             // full role feature length (W0T layout)
#define KPOFF 2048          // pair-GEMM feature base: [t*e | |t-e|]
#define NPAD 640
#define KC 64               // k per chunk
#define NCHUNK 32           // pair GEMM: K=2048 / 64
#define NTILES 5            // h tiles of 128

// smem geometry (bytes): A[128 rows][64 halves] pitch 144, B same shape
#define PITCH 144
#define A_BYTES (128 * PITCH)             // 18432
#define B_OFF   A_BYTES
#define STAGE_BYTES (2 * A_BYTES)         // 36864
#define SMEM_DYN (2 * STAGE_BYTES)        // 73728

// ---------------- scratch ----------------------------------------------------
__device__ float g_word[(size_t)BB * WW * DD];
__device__ float g_trig[(size_t)BB * TT * DD];
__device__ float g_ent [(size_t)BB * EE * DD];
__device__ __half g_W0T[(size_t)NPAD * KF];          // W0 transposed fp16 [n][k]
__device__ float g_Pt [(size_t)BB * TT * NPAD];      // t @ W0[0:D] + b0
__device__ float g_Pe [(size_t)BB * EE * NPAD];      // e @ W0[D:2D]
__device__ float g_part[(size_t)NTILES * BB * NPAIR * 2];

// ---------------- helpers ----------------------------------------------------
__device__ __forceinline__ void mma16816(float* c, const uint32_t* a, const uint32_t* b) {
    asm volatile(
        "mma.sync.aligned.m16n8k16.row.col.f32.f16.f16.f32 "
        "{%0,%1,%2,%3}, {%4,%5,%6,%7}, {%8,%9}, {%0,%1,%2,%3};"
        : "+f"(c[0]), "+f"(c[1]), "+f"(c[2]), "+f"(c[3])
        : "r"(a[0]), "r"(a[1]), "r"(a[2]), "r"(a[3]), "r"(b[0]), "r"(b[1]));
}
__device__ __forceinline__ void cp16(uint32_t dst, const void* src) {
    asm volatile("cp.async.ca.shared.global [%0], [%1], 16;" :: "r"(dst), "l"(src) : "memory");
}
__device__ __forceinline__ uint32_t smem_u32(const void* p) {
    uint32_t a;
    asm("{ .reg .u64 t; cvta.to.shared.u64 t, %1; cvt.u32.u64 %0, t; }"
        : "=r"(a) : "l"(p));
    return a;
}
__device__ __forceinline__ uint32_t pack_h2(float lo, float hi) {
    uint32_t r;
    asm("cvt.rn.f16x2.f32 %0, %1, %2;" : "=r"(r) : "f"(hi), "f"(lo));
    return r;
}

// ---------------- kernel 1: wordpiece -> word mean ---------------------------
__global__ void word_mean_kernel(const float* __restrict__ piece,
                                 const int* __restrict__ widx,
                                 float* __restrict__ out) {
    int w = blockIdx.x, b = blockIdx.y;
    int s = widx[(b * WW + w) * 2];
    int e = widx[(b * WW + w) * 2 + 1];
    float inv = 1.0f / (float)(e - s);
    const float* base = piece + (size_t)b * PP * DD;
    int t = threadIdx.x;
    float a0 = 0.f, a1 = 0.f, a2 = 0.f, a3 = 0.f;
    for (int r = s; r < e; r++) {
        float4 v = ((const float4*)(base + (size_t)r * DD))[t];
        a0 += v.x; a1 += v.y; a2 += v.z; a3 += v.w;
    }
    float4 o = make_float4(a0 * inv, a1 * inv, a2 * inv, a3 * inv);
    ((float4*)(out + (size_t)(b * WW + w) * DD))[t] = o;
}

// ---------------- kernel 2: word -> span mean --------------------------------
__global__ void span_mean_kernel(const float* __restrict__ words,
                                 const int* __restrict__ idx,
                                 float* __restrict__ out, int M) {
    int m = blockIdx.x, b = blockIdx.y;
    int s = idx[(b * M + m) * 2];
    int e = idx[(b * M + m) * 2 + 1];
    float inv = 1.0f / (float)(e - s);
    const float* base = words + (size_t)b * WW * DD;
    int t = threadIdx.x;
    float a0 = 0.f, a1 = 0.f, a2 = 0.f, a3 = 0.f;
    for (int r = s; r < e; r++) {
        float4 v = ((const float4*)(base + (size_t)r * DD))[t];
        a0 += v.x; a1 += v.y; a2 += v.z; a3 += v.w;
    }
    float4 o = make_float4(a0 * inv, a1 * inv, a2 * inv, a3 * inv);
    ((float4*)(out + (size_t)(b * M + m) * DD))[t] = o;
}

// ---------------- kernel 3: W0 [k][HH] -> W0T fp16 [NPAD][KF] ----------------
__global__ void bprep_kernel(const float* __restrict__ W0,
                             __half* __restrict__ W0T) {
    __shared__ float tile[32][33];
    int k0 = blockIdx.x * 32, n0 = blockIdx.y * 32;
    int x = threadIdx.x, y = threadIdx.y;
    float v = 0.f;
    if (n0 + x < HH) v = W0[(size_t)(k0 + y) * HH + (n0 + x)];
    tile[y][x] = v;
    __syncthreads();
    float w = tile[x][y];
    W0T[(size_t)(n0 + y) * KF + (k0 + x)] = __float2half_rn(w);
}

// ---------------- kernel 3b: P GEMM  C[M,640] = fp16(X[M,1024]) @ W0T[koff] --
// grid (NTILES, M/128), block 256, warp grid 2x4 (64x32 warp tile).
// Simple single-stage pipeline (K=1024 only).
__global__ __launch_bounds__(256)
void pgemm_kernel(const float* __restrict__ X,
                  const __half* __restrict__ W0T,
                  int koff,
                  const float* __restrict__ bias,
                  float* __restrict__ C) {
    __shared__ char psm[STAGE_BYTES];
    uint32_t sb = smem_u32(psm);
    int tid = threadIdx.x;
    int lane = tid & 31, warp = tid >> 5;
    int wm = warp >> 2, wn = warp & 3;
    int g = lane >> 2, t2 = (lane & 3) * 2;
    int nt = blockIdx.x, mt = blockIdx.y;
    int n0 = nt * 128, m0 = mt * 128;

    int prow = tid >> 1;
    int cb = (tid & 1) * 32;
    const float* xrow = X + (size_t)(m0 + prow) * DD;
    uint32_t aDst = sb + (uint32_t)prow * PITCH + cb * 2;
    uint32_t bDst = sb + B_OFF + (uint32_t)prow * PITCH + cb * 2;
    const __half* bSrcBase = W0T + (size_t)(n0 + prow) * KF + koff + cb;

    uint32_t aLd = sb + (uint32_t)(wm * 64 + g) * PITCH + (uint32_t)t2 * 2;
    uint32_t bLd = sb + B_OFF + (uint32_t)(wn * 32 + g) * PITCH + (uint32_t)t2 * 2;

    float acc[4][4][4];
#pragma unroll
    for (int i = 0; i < 4; i++)
#pragma unroll
        for (int j = 0; j < 4; j++)
#pragma unroll
            for (int q = 0; q < 4; q++) acc[i][j][q] = 0.f;

    for (int c = 0; c < DD / KC; c++) {
        // load X slice to regs, convert, store; B via cp.async
        float xv[32];
#pragma unroll
        for (int q = 0; q < 8; q++) {
            float4 v = ((const float4*)(xrow + c * KC + cb))[q];
            xv[q*4+0] = v.x; xv[q*4+1] = v.y; xv[q*4+2] = v.z; xv[q*4+3] = v.w;
        }
        const char* bs = (const char*)(bSrcBase + c * KC);
#pragma unroll
        for (int q = 0; q < 4; q++)
            cp16(bDst + q * 16, bs + q * 16);
#pragma unroll
        for (int gq = 0; gq < 4; gq++) {
            uint32_t p0 = pack_h2(xv[gq*8+0], xv[gq*8+1]);
            uint32_t p1 = pack_h2(xv[gq*8+2], xv[gq*8+3]);
            uint32_t p2 = pack_h2(xv[gq*8+4], xv[gq*8+5]);
            uint32_t p3 = pack_h2(xv[gq*8+6], xv[gq*8+7]);
            asm volatile("st.shared.v4.b32 [%0], {%1,%2,%3,%4};"
                         :: "r"(aDst + gq * 16), "r"(p0), "r"(p1), "r"(p2), "r"(p3) : "memory");
        }
        asm volatile("cp.async.wait_all;" ::: "memory");
        __syncthreads();
#pragma unroll
        for (int ks = 0; ks < 4; ks++) {
            uint32_t afr[4][4], bfr[4][2];
            uint32_t aO = aLd + (uint32_t)ks * 32;
            uint32_t bO = bLd + (uint32_t)ks * 32;
#pragma unroll
            for (int j = 0; j < 4; j++) {
                uint32_t o = bO + (uint32_t)j * (8 * PITCH);
                asm volatile("ld.shared.b32 %0, [%1];" : "=r"(bfr[j][0]) : "r"(o));
                asm volatile("ld.shared.b32 %0, [%1];" : "=r"(bfr[j][1]) : "r"(o + 16));
            }
#pragma unroll
            for (int i = 0; i < 4; i++) {
                uint32_t o = aO + (uint32_t)i * (16 * PITCH);
                asm volatile("ld.shared.b32 %0, [%1];" : "=r"(afr[i][0]) : "r"(o));
                asm volatile("ld.shared.b32 %0, [%1];" : "=r"(afr[i][1]) : "r"(o + 8 * PITCH));
                asm volatile("ld.shared.b32 %0, [%1];" : "=r"(afr[i][2]) : "r"(o + 16));
                asm volatile("ld.shared.b32 %0, [%1];" : "=r"(afr[i][3]) : "r"(o + 8 * PITCH + 16));
            }
#pragma unroll
            for (int i = 0; i < 4; i++)
#pragma unroll
                for (int j = 0; j < 4; j++)
                    mma16816(acc[i][j], afr[i], bfr[j]);
        }
        __syncthreads();
    }

    // store C (+bias for Pt)
#pragma unroll
    for (int j = 0; j < 4; j++) {
        int hcol = n0 + wn * 32 + j * 8 + t2;
#pragma unroll
        for (int cp = 0; cp < 2; cp++) {
            int h = hcol + cp;
            float bb = (bias && h < HH) ? bias[h] : 0.f;
#pragma unroll
            for (int i = 0; i < 4; i++) {
                int r0 = m0 + wm * 64 + i * 16 + g;
                C[(size_t)r0 * NPAD + h]       = acc[i][j][cp] + bb;
                C[(size_t)(r0 + 8) * NPAD + h] = acc[i][j][2 + cp] + bb;
            }
        }
    }
}

// ---------------- kernel 4: fused pair GEMM (K=2048: t*e | |t-e|) ------------
// grid (NTILES, TT/2, BB), block 256 (8 warps, warp grid 2x4).
// Epilogue: acc + Pt + Pe, relu, @W1 -> per-ntile partials.
__global__ __launch_bounds__(256)
void pair_mma_kernel(const float* __restrict__ trig,
                     const float* __restrict__ ent,
                     const __half* __restrict__ W0T,
                     const float* __restrict__ Pt,
                     const float* __restrict__ Pe,
                     const float* __restrict__ W1,
                     float* __restrict__ part) {
    extern __shared__ char dsm[];
    __shared__ float trig_s[2 * DD];
    __shared__ float red[128][4][2];

    uint32_t sb = smem_u32(dsm);
    int tid = threadIdx.x;
    int lane = tid & 31, warp = tid >> 5;
    int wm = warp >> 2, wn = warp & 3;
    int g = lane >> 2, t2 = (lane & 3) * 2;
    int nt = blockIdx.x, mt = blockIdx.y, b = blockIdx.z;
    int n0 = nt * 128;

    {
        const float4* src = (const float4*)(trig + (size_t)(b * TT + 2 * mt) * DD);
        ((float4*)trig_s)[tid]       = src[tid];
        ((float4*)trig_s)[tid + 256] = src[tid + 256];
    }

    int prow = tid >> 1;
    int cb = (tid & 1) * 32;
    int tl = prow >> 6, ei = prow & 63;
    const float* trow = trig_s + tl * DD;
    const float* erow = ent + (size_t)(b * EE + ei) * DD;
    uint32_t aDst = sb + (uint32_t)prow * PITCH + cb * 2;
    uint32_t bDst = sb + B_OFF + (uint32_t)prow * PITCH + cb * 2;
    const __half* bSrcBase = W0T + (size_t)(n0 + prow) * KF + KPOFF + cb;

    uint32_t aLd = sb + (uint32_t)(wm * 64 + g) * PITCH + (uint32_t)t2 * 2;
    uint32_t bLd = sb + B_OFF + (uint32_t)(wn * 32 + g) * PITCH + (uint32_t)t2 * 2;

    float acc[4][4][4];
#pragma unroll
    for (int i = 0; i < 4; i++)
#pragma unroll
        for (int j = 0; j < 4; j++)
#pragma unroll
            for (int q = 0; q < 4; q++) acc[i][j][q] = 0.f;

    __syncthreads();   // trig_s ready

    // ---- prologue: chunk 0 = product block, k [0,64)
    {
        float va[32];
#pragma unroll
        for (int q = 0; q < 8; q++) {
            float4 v = ((const float4*)(erow + cb))[q];
            va[q*4+0] = v.x; va[q*4+1] = v.y; va[q*4+2] = v.z; va[q*4+3] = v.w;
        }
#pragma unroll
        for (int j = 0; j < 32; j++) va[j] *= trow[cb + j];
#pragma unroll
        for (int gq = 0; gq < 4; gq++) {
            uint32_t p0 = pack_h2(va[gq*8+0], va[gq*8+1]);
            uint32_t p1 = pack_h2(va[gq*8+2], va[gq*8+3]);
            uint32_t p2 = pack_h2(va[gq*8+4], va[gq*8+5]);
            uint32_t p3 = pack_h2(va[gq*8+6], va[gq*8+7]);
            asm volatile("st.shared.v4.b32 [%0], {%1,%2,%3,%4};"
                         :: "r"(aDst + gq * 16), "r"(p0), "r"(p1), "r"(p2), "r"(p3) : "memory");
        }
#pragma unroll
        for (int q = 0; q < 4; q++)
            cp16(bDst + q * 16, (const char*)bSrcBase + q * 16);
        asm volatile("cp.async.wait_all;" ::: "memory");
    }
    __syncthreads();

    // ---- main loop over 32 chunks
    for (int c = 0; c < NCHUNK; c++) {
        uint32_t stageOff = (uint32_t)(c & 1) * STAGE_BYTES;
        int cn = c + 1;
        int blkN = cn >> 4, kkN = (cn & 15) * KC;
        uint32_t nStage = (uint32_t)(cn & 1) * STAGE_BYTES;
        float ev[32];

        // P1: prefetch next-chunk ent slice + B cp.async
        if (cn < NCHUNK) {
#pragma unroll
            for (int q = 0; q < 8; q++) {
                float4 v = ((const float4*)(erow + kkN + cb))[q];
                ev[q*4+0] = v.x; ev[q*4+1] = v.y; ev[q*4+2] = v.z; ev[q*4+3] = v.w;
            }
            const char* bs = (const char*)(bSrcBase + cn * KC);
#pragma unroll
            for (int q = 0; q < 4; q++)
                cp16(bDst + nStage + q * 16, bs + q * 16);
        }

        // MMA: 4 k-steps over current stage
#pragma unroll
        for (int ks = 0; ks < 4; ks++) {
            uint32_t afr[4][4], bfr[4][2];
            uint32_t aO = aLd + stageOff + (uint32_t)ks * 32;
            uint32_t bO = bLd + stageOff + (uint32_t)ks * 32;
#pragma unroll
            for (int j = 0; j < 4; j++) {
                uint32_t o = bO + (uint32_t)j * (8 * PITCH);
                asm volatile("ld.shared.b32 %0, [%1];" : "=r"(bfr[j][0]) : "r"(o));
                asm volatile("ld.shared.b32 %0, [%1];" : "=r"(bfr[j][1]) : "r"(o + 16));
            }
#pragma unroll
            for (int i = 0; i < 4; i++) {
                uint32_t o = aO + (uint32_t)i * (16 * PITCH);
                asm volatile("ld.shared.b32 %0, [%1];" : "=r"(afr[i][0]) : "r"(o));
                asm volatile("ld.shared.b32 %0, [%1];" : "=r"(afr[i][1]) : "r"(o + 8 * PITCH));
                asm volatile("ld.shared.b32 %0, [%1];" : "=r"(afr[i][2]) : "r"(o + 16));
                asm volatile("ld.shared.b32 %0, [%1];" : "=r"(afr[i][3]) : "r"(o + 8 * PITCH + 16));
            }
#pragma unroll
            for (int i = 0; i < 4; i++)
#pragma unroll
                for (int j = 0; j < 4; j++)
                    mma16816(acc[i][j], afr[i], bfr[j]);
        }

        // P2: convert + store next-chunk A (blk 0 = product, blk 1 = absdiff)
        if (cn < NCHUNK) {
            float va[32];
            if (blkN == 0) {
#pragma unroll
                for (int j = 0; j < 32; j++) va[j] = trow[kkN + cb + j] * ev[j];
            } else {
#pragma unroll
                for (int j = 0; j < 32; j++) va[j] = fabsf(trow[kkN + cb + j] - ev[j]);
            }
            uint32_t dst = aDst + nStage;
#pragma unroll
            for (int gq = 0; gq < 4; gq++) {
                uint32_t p0 = pack_h2(va[gq*8+0], va[gq*8+1]);
                uint32_t p1 = pack_h2(va[gq*8+2], va[gq*8+3]);
                uint32_t p2 = pack_h2(va[gq*8+4], va[gq*8+5]);
                uint32_t p3 = pack_h2(va[gq*8+6], va[gq*8+7]);
                asm volatile("st.shared.v4.b32 [%0], {%1,%2,%3,%4};"
                             :: "r"(dst + gq * 16), "r"(p0), "r"(p1), "r"(p2), "r"(p3) : "memory");
            }
            asm volatile("cp.async.wait_all;" ::: "memory");
        }
        __syncthreads();
    }

    // ---- epilogue: acc + Pt + Pe, relu, @W1 -> per-row partials
    float pr[4][2][2];
#pragma unroll
    for (int i = 0; i < 4; i++)
#pragma unroll
        for (int hh = 0; hh < 2; hh++) { pr[i][hh][0] = 0.f; pr[i][hh][1] = 0.f; }

    const float* ptRow = Pt + (size_t)(b * TT + 2 * mt + wm) * NPAD;
    const float* peBase = Pe + (size_t)(b * EE) * NPAD;

#pragma unroll
    for (int j = 0; j < 4; j++) {
        int hcol = n0 + wn * 32 + j * 8 + t2;
#pragma unroll
        for (int cp = 0; cp < 2; cp++) {
            int h = hcol + cp;
            if (h < HH) {
                float pt = ptRow[h];
                float w10 = W1[2 * h], w11 = W1[2 * h + 1];
#pragma unroll
                for (int i = 0; i < 4; i++) {
                    float pe0 = peBase[(size_t)(i * 16 + g) * NPAD + h];
                    float pe1 = peBase[(size_t)(i * 16 + g + 8) * NPAD + h];
                    float v0 = fmaxf(acc[i][j][cp] + pt + pe0, 0.f);
                    float v1 = fmaxf(acc[i][j][2 + cp] + pt + pe1, 0.f);
                    pr[i][0][0] = fmaf(v0, w10, pr[i][0][0]);
                    pr[i][0][1] = fmaf(v0, w11, pr[i][0][1]);
                    pr[i][1][0] = fmaf(v1, w10, pr[i][1][0]);
                    pr[i][1][1] = fmaf(v1, w11, pr[i][1][1]);
                }
            }
        }
    }
#pragma unroll
    for (int i = 0; i < 4; i++)
#pragma unroll
        for (int hh = 0; hh < 2; hh++)
#pragma unroll
            for (int o = 0; o < 2; o++) {
                float v = pr[i][hh][o];
                v += __shfl_xor_sync(0xffffffffu, v, 1);
                v += __shfl_xor_sync(0xffffffffu, v, 2);
                pr[i][hh][o] = v;
            }
    if ((lane & 3) == 0) {
#pragma unroll
        for (int i = 0; i < 4; i++)
#pragma unroll
            for (int hh = 0; hh < 2; hh++) {
                int row = wm * 64 + i * 16 + g + hh * 8;
                red[row][wn][0] = pr[i][hh][0];
                red[row][wn][1] = pr[i][hh][1];
            }
    }
    __syncthreads();
    if (tid < 128) {
        int row = tid;
        float a0 = 0.f, a1 = 0.f;
#pragma unroll
        for (int wc = 0; wc < 4; wc++) {
            a0 += red[row][wc][0];
            a1 += red[row][wc][1];
        }
        int pair = (2 * mt + (row >> 6)) * EE + (row & 63);
        size_t oidx = ((size_t)nt * BB * NPAIR + (size_t)b * NPAIR + pair) * 2;
        part[oidx]     = a0;
        part[oidx + 1] = a1;
    }
}

// ---------------- kernel 5: reduce 5 partials + b1 ---------------------------
__global__ void reduce_out_kernel(const float* __restrict__ part,
                                  const float* __restrict__ b1,
                                  float* __restrict__ out) {
    int i = blockIdx.x * blockDim.x + threadIdx.x;
    float a = b1[i & 1];
#pragma unroll
    for (int t = 0; t < NTILES; t++)
        a += part[(size_t)t * BB * NPAIR * 2 + i];
    out[i] = a;
}

// ---------------- launch -----------------------------------------------------
extern "C" void kernel_launch(void* const* d_in, const int* in_sizes, int n_in,
                              void* d_out, int out_size) {
    const float* piece = (const float*)d_in[0];
    const int*   widx  = (const int*)d_in[1];
    const int*   tidx  = (const int*)d_in[2];
    const int*   eidx  = (const int*)d_in[3];
    const float* W0    = (const float*)d_in[4];
    const float* b0    = (const float*)d_in[5];
    const float* W1    = (const float*)d_in[6];
    const float* b1    = (const float*)d_in[7];
    float* out = (float*)d_out;

    float *wordp, *trigp, *entp, *ptp, *pep, *partp;
    __half* w0tp;
    cudaGetSymbolAddress((void**)&wordp, g_word);
    cudaGetSymbolAddress((void**)&trigp, g_trig);
    cudaGetSymbolAddress((void**)&entp,  g_ent);
    cudaGetSymbolAddress((void**)&w0tp,  g_W0T);
    cudaGetSymbolAddress((void**)&ptp,   g_Pt);
    cudaGetSymbolAddress((void**)&pep,   g_Pe);
    cudaGetSymbolAddress((void**)&partp, g_part);

    cudaFuncSetAttribute(pair_mma_kernel,
                         cudaFuncAttributeMaxDynamicSharedMemorySize, SMEM_DYN);

    word_mean_kernel<<<dim3(WW, BB), 256>>>(piece, widx, wordp);
    span_mean_kernel<<<dim3(TT, BB), 256>>>(wordp, tidx, trigp, TT);
    span_mean_kernel<<<dim3(EE, BB), 256>>>(wordp, eidx, entp, EE);
    bprep_kernel<<<dim3(KF / 32, NPAD / 32), dim3(32, 32)>>>(W0, w0tp);
    // Pt = trig @ W0[0:D] + b0  (M = 512)
    pgemm_kernel<<<dim3(NTILES, (BB * TT) / 128), 256>>>(trigp, w0tp, 0, b0, ptp);
    // Pe = ent @ W0[D:2D]       (M = 1024)
    pgemm_kernel<<<dim3(NTILES, (BB * EE) / 128), 256>>>(entp, w0tp, DD, nullptr, pep);
    pair_mma_kernel<<<dim3(NTILES, TT / 2, BB), 256, SMEM_DYN>>>(
        trigp, entp, w0tp, ptp, pep, W1, partp);
    reduce_out_kernel<<<(BB * NPAIR * 2) / 1024, 1024>>>(partp, b1, out);
    (void)in_sizes; (void)n_in; (void)out_size;
}

// round 7
// speedup vs baseline: 3.5831x; 1.0851x over previous
#include <cuda_runtime.h>
#include <cuda_fp16.h>
#include <math.h>
#include <stdint.h>

// Problem constants
#define BB 16
#define PP 512
#define DD 1024
#define WW 400
#define TT 32
#define EE 64
#define HH 600
#define NPAIR (TT * EE)     // 2048
#define KF 4096             // full role feature length (W0T layout)
#define KPOFF 2048          // pair-GEMM feature base: [t*e | |t-e|]
#define NPAD 640
#define KC 64               // k per chunk
#define NCHUNK 32           // pair GEMM: K=2048 / 64
#define NTILES 5            // h tiles of 128

// smem geometry (bytes): A[128 rows][64 halves] pitch 144, B same shape
#define PITCH 144
#define A_BYTES (128 * PITCH)             // 18432
#define B_OFF   A_BYTES
#define STAGE_BYTES (2 * A_BYTES)         // 36864
#define SMEM_DYN (2 * STAGE_BYTES)        // 73728

// ---------------- scratch ----------------------------------------------------
__device__ float g_word[(size_t)BB * WW * DD];
__device__ float g_trig[(size_t)BB * TT * DD];
__device__ float g_ent [(size_t)BB * EE * DD];
__device__ __half g_W0T[(size_t)NPAD * KF];          // W0 transposed fp16 [n][k]
__device__ float g_Pt [(size_t)BB * TT * NPAD];      // t @ W0[0:D] + b0
__device__ float g_Pe [(size_t)BB * EE * NPAD];      // e @ W0[D:2D]
__device__ float g_part[(size_t)NTILES * BB * NPAIR * 2];

// ---------------- helpers ----------------------------------------------------
__device__ __forceinline__ void mma16816(float* c, const uint32_t* a, const uint32_t* b) {
    asm volatile(
        "mma.sync.aligned.m16n8k16.row.col.f32.f16.f16.f32 "
        "{%0,%1,%2,%3}, {%4,%5,%6,%7}, {%8,%9}, {%0,%1,%2,%3};"
        : "+f"(c[0]), "+f"(c[1]), "+f"(c[2]), "+f"(c[3])
        : "r"(a[0]), "r"(a[1]), "r"(a[2]), "r"(a[3]), "r"(b[0]), "r"(b[1]));
}
__device__ __forceinline__ void cp16(uint32_t dst, const void* src) {
    asm volatile("cp.async.ca.shared.global [%0], [%1], 16;" :: "r"(dst), "l"(src) : "memory");
}
__device__ __forceinline__ uint32_t smem_u32(const void* p) {
    uint32_t a;
    asm("{ .reg .u64 t; cvta.to.shared.u64 t, %1; cvt.u32.u64 %0, t; }"
        : "=r"(a) : "l"(p));
    return a;
}
__device__ __forceinline__ uint32_t pack_h2(float lo, float hi) {
    uint32_t r;
    asm("cvt.rn.f16x2.f32 %0, %1, %2;" : "=r"(r) : "f"(hi), "f"(lo));
    return r;
}

// ---------------- kernel 1: wordpiece -> word mean ---------------------------
__global__ void word_mean_kernel(const float* __restrict__ piece,
                                 const int* __restrict__ widx,
                                 float* __restrict__ out) {
    int w = blockIdx.x, b = blockIdx.y;
    int s = widx[(b * WW + w) * 2];
    int e = widx[(b * WW + w) * 2 + 1];
    float inv = 1.0f / (float)(e - s);
    const float* base = piece + (size_t)b * PP * DD;
    int t = threadIdx.x;
    float a0 = 0.f, a1 = 0.f, a2 = 0.f, a3 = 0.f;
    for (int r = s; r < e; r++) {
        float4 v = ((const float4*)(base + (size_t)r * DD))[t];
        a0 += v.x; a1 += v.y; a2 += v.z; a3 += v.w;
    }
    float4 o = make_float4(a0 * inv, a1 * inv, a2 * inv, a3 * inv);
    ((float4*)(out + (size_t)(b * WW + w) * DD))[t] = o;
}

// ---------------- kernel 2: word -> span mean --------------------------------
__global__ void span_mean_kernel(const float* __restrict__ words,
                                 const int* __restrict__ idx,
                                 float* __restrict__ out, int M) {
    int m = blockIdx.x, b = blockIdx.y;
    int s = idx[(b * M + m) * 2];
    int e = idx[(b * M + m) * 2 + 1];
    float inv = 1.0f / (float)(e - s);
    const float* base = words + (size_t)b * WW * DD;
    int t = threadIdx.x;
    float a0 = 0.f, a1 = 0.f, a2 = 0.f, a3 = 0.f;
    for (int r = s; r < e; r++) {
        float4 v = ((const float4*)(base + (size_t)r * DD))[t];
        a0 += v.x; a1 += v.y; a2 += v.z; a3 += v.w;
    }
    float4 o = make_float4(a0 * inv, a1 * inv, a2 * inv, a3 * inv);
    ((float4*)(out + (size_t)(b * M + m) * DD))[t] = o;
}

// ---------------- kernel 3: W0 [k][HH] -> W0T fp16 [NPAD][KF] ----------------
__global__ void bprep_kernel(const float* __restrict__ W0,
                             __half* __restrict__ W0T) {
    __shared__ float tile[32][33];
    int k0 = blockIdx.x * 32, n0 = blockIdx.y * 32;
    int x = threadIdx.x, y = threadIdx.y;
    float v = 0.f;
    if (n0 + x < HH) v = W0[(size_t)(k0 + y) * HH + (n0 + x)];
    tile[y][x] = v;
    __syncthreads();
    float w = tile[x][y];
    W0T[(size_t)(n0 + y) * KF + (k0 + x)] = __float2half_rn(w);
}

// ---------------- kernel 3b: P GEMM  C[M,640] = fp16(X[M,1024]) @ W0T[koff] --
__global__ __launch_bounds__(256)
void pgemm_kernel(const float* __restrict__ X,
                  const __half* __restrict__ W0T,
                  int koff,
                  const float* __restrict__ bias,
                  float* __restrict__ C) {
    __shared__ char psm[STAGE_BYTES];
    uint32_t sb = smem_u32(psm);
    int tid = threadIdx.x;
    int lane = tid & 31, warp = tid >> 5;
    int wm = warp >> 2, wn = warp & 3;
    int g = lane >> 2, t2 = (lane & 3) * 2;
    int nt = blockIdx.x, mt = blockIdx.y;
    int n0 = nt * 128, m0 = mt * 128;

    int prow = tid >> 1;
    int cb = (tid & 1) * 32;
    const float* xrow = X + (size_t)(m0 + prow) * DD;
    uint32_t aDst = sb + (uint32_t)prow * PITCH + cb * 2;
    uint32_t bDst = sb + B_OFF + (uint32_t)prow * PITCH + cb * 2;
    const __half* bSrcBase = W0T + (size_t)(n0 + prow) * KF + koff + cb;

    uint32_t aLd = sb + (uint32_t)(wm * 64 + g) * PITCH + (uint32_t)t2 * 2;
    uint32_t bLd = sb + B_OFF + (uint32_t)(wn * 32 + g) * PITCH + (uint32_t)t2 * 2;

    float acc[4][4][4];
#pragma unroll
    for (int i = 0; i < 4; i++)
#pragma unroll
        for (int j = 0; j < 4; j++)
#pragma unroll
            for (int q = 0; q < 4; q++) acc[i][j][q] = 0.f;

    for (int c = 0; c < DD / KC; c++) {
        float xv[32];
#pragma unroll
        for (int q = 0; q < 8; q++) {
            float4 v = ((const float4*)(xrow + c * KC + cb))[q];
            xv[q*4+0] = v.x; xv[q*4+1] = v.y; xv[q*4+2] = v.z; xv[q*4+3] = v.w;
        }
        const char* bs = (const char*)(bSrcBase + c * KC);
#pragma unroll
        for (int q = 0; q < 4; q++)
            cp16(bDst + q * 16, bs + q * 16);
#pragma unroll
        for (int gq = 0; gq < 4; gq++) {
            uint32_t p0 = pack_h2(xv[gq*8+0], xv[gq*8+1]);
            uint32_t p1 = pack_h2(xv[gq*8+2], xv[gq*8+3]);
            uint32_t p2 = pack_h2(xv[gq*8+4], xv[gq*8+5]);
            uint32_t p3 = pack_h2(xv[gq*8+6], xv[gq*8+7]);
            asm volatile("st.shared.v4.b32 [%0], {%1,%2,%3,%4};"
                         :: "r"(aDst + gq * 16), "r"(p0), "r"(p1), "r"(p2), "r"(p3) : "memory");
        }
        asm volatile("cp.async.wait_all;" ::: "memory");
        __syncthreads();
#pragma unroll
        for (int ks = 0; ks < 4; ks++) {
            uint32_t afr[4][4], bfr[4][2];
            uint32_t aO = aLd + (uint32_t)ks * 32;
            uint32_t bO = bLd + (uint32_t)ks * 32;
#pragma unroll
            for (int j = 0; j < 4; j++) {
                uint32_t o = bO + (uint32_t)j * (8 * PITCH);
                asm volatile("ld.shared.b32 %0, [%1];" : "=r"(bfr[j][0]) : "r"(o));
                asm volatile("ld.shared.b32 %0, [%1];" : "=r"(bfr[j][1]) : "r"(o + 16));
            }
#pragma unroll
            for (int i = 0; i < 4; i++) {
                uint32_t o = aO + (uint32_t)i * (16 * PITCH);
                asm volatile("ld.shared.b32 %0, [%1];" : "=r"(afr[i][0]) : "r"(o));
                asm volatile("ld.shared.b32 %0, [%1];" : "=r"(afr[i][1]) : "r"(o + 8 * PITCH));
                asm volatile("ld.shared.b32 %0, [%1];" : "=r"(afr[i][2]) : "r"(o + 16));
                asm volatile("ld.shared.b32 %0, [%1];" : "=r"(afr[i][3]) : "r"(o + 8 * PITCH + 16));
            }
#pragma unroll
            for (int i = 0; i < 4; i++)
#pragma unroll
                for (int j = 0; j < 4; j++)
                    mma16816(acc[i][j], afr[i], bfr[j]);
        }
        __syncthreads();
    }

#pragma unroll
    for (int j = 0; j < 4; j++) {
        int hcol = n0 + wn * 32 + j * 8 + t2;
#pragma unroll
        for (int cp = 0; cp < 2; cp++) {
            int h = hcol + cp;
            float bb = (bias && h < HH) ? bias[h] : 0.f;
#pragma unroll
            for (int i = 0; i < 4; i++) {
                int r0 = m0 + wm * 64 + i * 16 + g;
                C[(size_t)r0 * NPAD + h]       = acc[i][j][cp] + bb;
                C[(size_t)(r0 + 8) * NPAD + h] = acc[i][j][2 + cp] + bb;
            }
        }
    }
}

// ---------------- kernel 4: fused pair GEMM (K=2048: t*e | |t-e|) ------------
// grid (NTILES, TT/2, BB), block 256 (8 warps, warp grid 2x4), 2 CTAs/SM.
// Epilogue: acc + Pt + Pe, relu, @W1 -> per-ntile partials.
__global__ __launch_bounds__(256, 2)
void pair_mma_kernel(const float* __restrict__ trig,
                     const float* __restrict__ ent,
                     const __half* __restrict__ W0T,
                     const float* __restrict__ Pt,
                     const float* __restrict__ Pe,
                     const float* __restrict__ W1,
                     float* __restrict__ part) {
    extern __shared__ char dsm[];
    __shared__ float trig_s[2 * DD];
    __shared__ float red[128][4][2];

    uint32_t sb = smem_u32(dsm);
    int tid = threadIdx.x;
    int lane = tid & 31, warp = tid >> 5;
    int wm = warp >> 2, wn = warp & 3;
    int g = lane >> 2, t2 = (lane & 3) * 2;
    int nt = blockIdx.x, mt = blockIdx.y, b = blockIdx.z;
    int n0 = nt * 128;

    {
        const float4* src = (const float4*)(trig + (size_t)(b * TT + 2 * mt) * DD);
        ((float4*)trig_s)[tid]       = src[tid];
        ((float4*)trig_s)[tid + 256] = src[tid + 256];
    }

    int prow = tid >> 1;
    int cb = (tid & 1) * 32;
    int tl = prow >> 6, ei = prow & 63;
    const float* trow = trig_s + tl * DD;
    const float* erow = ent + (size_t)(b * EE + ei) * DD;
    uint32_t aDst = sb + (uint32_t)prow * PITCH + cb * 2;
    uint32_t bDst = sb + B_OFF + (uint32_t)prow * PITCH + cb * 2;
    const __half* bSrcBase = W0T + (size_t)(n0 + prow) * KF + KPOFF + cb;

    uint32_t aLd = sb + (uint32_t)(wm * 64 + g) * PITCH + (uint32_t)t2 * 2;
    uint32_t bLd = sb + B_OFF + (uint32_t)(wn * 32 + g) * PITCH + (uint32_t)t2 * 2;

    float acc[4][4][4];
#pragma unroll
    for (int i = 0; i < 4; i++)
#pragma unroll
        for (int j = 0; j < 4; j++)
#pragma unroll
            for (int q = 0; q < 4; q++) acc[i][j][q] = 0.f;

    __syncthreads();   // trig_s ready

    // ---- prologue: chunk 0 = product block, k [0,64)
    {
        const float4* esrc = (const float4*)(erow + cb);
        const float* tr = trow + cb;
#pragma unroll
        for (int gq = 0; gq < 4; gq++) {
            float4 e0 = esrc[gq * 2], e1 = esrc[gq * 2 + 1];
            const float* tt = tr + gq * 8;
            uint32_t p0 = pack_h2(tt[0] * e0.x, tt[1] * e0.y);
            uint32_t p1 = pack_h2(tt[2] * e0.z, tt[3] * e0.w);
            uint32_t p2 = pack_h2(tt[4] * e1.x, tt[5] * e1.y);
            uint32_t p3 = pack_h2(tt[6] * e1.z, tt[7] * e1.w);
            asm volatile("st.shared.v4.b32 [%0], {%1,%2,%3,%4};"
                         :: "r"(aDst + gq * 16), "r"(p0), "r"(p1), "r"(p2), "r"(p3) : "memory");
        }
#pragma unroll
        for (int q = 0; q < 4; q++)
            cp16(bDst + q * 16, (const char*)bSrcBase + q * 16);
        asm volatile("cp.async.wait_all;" ::: "memory");
    }
    __syncthreads();

    // ---- main loop over 32 chunks
    for (int c = 0; c < NCHUNK; c++) {
        uint32_t stageOff = (uint32_t)(c & 1) * STAGE_BYTES;
        int cn = c + 1;
        int blkN = cn >> 4, kkN = (cn & 15) * KC;
        uint32_t nStage = (uint32_t)(cn & 1) * STAGE_BYTES;

        // P1: issue B cp.async for next chunk
        if (cn < NCHUNK) {
            const char* bs = (const char*)(bSrcBase + cn * KC);
#pragma unroll
            for (int q = 0; q < 4; q++)
                cp16(bDst + nStage + q * 16, bs + q * 16);
        }

        // MMA: 4 k-steps over current stage
#pragma unroll
        for (int ks = 0; ks < 4; ks++) {
            uint32_t afr[4][4], bfr[4][2];
            uint32_t aO = aLd + stageOff + (uint32_t)ks * 32;
            uint32_t bO = bLd + stageOff + (uint32_t)ks * 32;
#pragma unroll
            for (int j = 0; j < 4; j++) {
                uint32_t o = bO + (uint32_t)j * (8 * PITCH);
                asm volatile("ld.shared.b32 %0, [%1];" : "=r"(bfr[j][0]) : "r"(o));
                asm volatile("ld.shared.b32 %0, [%1];" : "=r"(bfr[j][1]) : "r"(o + 16));
            }
#pragma unroll
            for (int i = 0; i < 4; i++) {
                uint32_t o = aO + (uint32_t)i * (16 * PITCH);
                asm volatile("ld.shared.b32 %0, [%1];" : "=r"(afr[i][0]) : "r"(o));
                asm volatile("ld.shared.b32 %0, [%1];" : "=r"(afr[i][1]) : "r"(o + 8 * PITCH));
                asm volatile("ld.shared.b32 %0, [%1];" : "=r"(afr[i][2]) : "r"(o + 16));
                asm volatile("ld.shared.b32 %0, [%1];" : "=r"(afr[i][3]) : "r"(o + 8 * PITCH + 16));
            }
#pragma unroll
            for (int i = 0; i < 4; i++)
#pragma unroll
                for (int j = 0; j < 4; j++)
                    mma16816(acc[i][j], afr[i], bfr[j]);
        }

        // P2: generate next-chunk A straight from gmem (ent is L2-resident)
        if (cn < NCHUNK) {
            const float4* esrc = (const float4*)(erow + kkN + cb);
            const float* tr = trow + kkN + cb;
            uint32_t dst = aDst + nStage;
            if (blkN == 0) {
#pragma unroll
                for (int gq = 0; gq < 4; gq++) {
                    float4 e0 = esrc[gq * 2], e1 = esrc[gq * 2 + 1];
                    const float* tt = tr + gq * 8;
                    uint32_t p0 = pack_h2(tt[0] * e0.x, tt[1] * e0.y);
                    uint32_t p1 = pack_h2(tt[2] * e0.z, tt[3] * e0.w);
                    uint32_t p2 = pack_h2(tt[4] * e1.x, tt[5] * e1.y);
                    uint32_t p3 = pack_h2(tt[6] * e1.z, tt[7] * e1.w);
                    asm volatile("st.shared.v4.b32 [%0], {%1,%2,%3,%4};"
                                 :: "r"(dst + gq * 16), "r"(p0), "r"(p1), "r"(p2), "r"(p3) : "memory");
                }
            } else {
#pragma unroll
                for (int gq = 0; gq < 4; gq++) {
                    float4 e0 = esrc[gq * 2], e1 = esrc[gq * 2 + 1];
                    const float* tt = tr + gq * 8;
                    uint32_t p0 = pack_h2(fabsf(tt[0] - e0.x), fabsf(tt[1] - e0.y));
                    uint32_t p1 = pack_h2(fabsf(tt[2] - e0.z), fabsf(tt[3] - e0.w));
                    uint32_t p2 = pack_h2(fabsf(tt[4] - e1.x), fabsf(tt[5] - e1.y));
                    uint32_t p3 = pack_h2(fabsf(tt[6] - e1.z), fabsf(tt[7] - e1.w));
                    asm volatile("st.shared.v4.b32 [%0], {%1,%2,%3,%4};"
                                 :: "r"(dst + gq * 16), "r"(p0), "r"(p1), "r"(p2), "r"(p3) : "memory");
                }
            }
            asm volatile("cp.async.wait_all;" ::: "memory");
        }
        __syncthreads();
    }

    // ---- epilogue: acc + Pt + Pe, relu, @W1 -> per-row partials
    float pr[4][2][2];
#pragma unroll
    for (int i = 0; i < 4; i++)
#pragma unroll
        for (int hh = 0; hh < 2; hh++) { pr[i][hh][0] = 0.f; pr[i][hh][1] = 0.f; }

    const float* ptRow = Pt + (size_t)(b * TT + 2 * mt + wm) * NPAD;
    const float* peBase = Pe + (size_t)(b * EE) * NPAD;

#pragma unroll
    for (int j = 0; j < 4; j++) {
        int hcol = n0 + wn * 32 + j * 8 + t2;
#pragma unroll
        for (int cp = 0; cp < 2; cp++) {
            int h = hcol + cp;
            if (h < HH) {
                float pt = ptRow[h];
                float w10 = W1[2 * h], w11 = W1[2 * h + 1];
#pragma unroll
                for (int i = 0; i < 4; i++) {
                    float pe0 = peBase[(size_t)(i * 16 + g) * NPAD + h];
                    float pe1 = peBase[(size_t)(i * 16 + g + 8) * NPAD + h];
                    float v0 = fmaxf(acc[i][j][cp] + pt + pe0, 0.f);
                    float v1 = fmaxf(acc[i][j][2 + cp] + pt + pe1, 0.f);
                    pr[i][0][0] = fmaf(v0, w10, pr[i][0][0]);
                    pr[i][0][1] = fmaf(v0, w11, pr[i][0][1]);
                    pr[i][1][0] = fmaf(v1, w10, pr[i][1][0]);
                    pr[i][1][1] = fmaf(v1, w11, pr[i][1][1]);
                }
            }
        }
    }
#pragma unroll
    for (int i = 0; i < 4; i++)
#pragma unroll
        for (int hh = 0; hh < 2; hh++)
#pragma unroll
            for (int o = 0; o < 2; o++) {
                float v = pr[i][hh][o];
                v += __shfl_xor_sync(0xffffffffu, v, 1);
                v += __shfl_xor_sync(0xffffffffu, v, 2);
                pr[i][hh][o] = v;
            }
    if ((lane & 3) == 0) {
#pragma unroll
        for (int i = 0; i < 4; i++)
#pragma unroll
            for (int hh = 0; hh < 2; hh++) {
                int row = wm * 64 + i * 16 + g + hh * 8;
                red[row][wn][0] = pr[i][hh][0];
                red[row][wn][1] = pr[i][hh][1];
            }
    }
    __syncthreads();
    if (tid < 128) {
        int row = tid;
        float a0 = 0.f, a1 = 0.f;
#pragma unroll
        for (int wc = 0; wc < 4; wc++) {
            a0 += red[row][wc][0];
            a1 += red[row][wc][1];
        }
        int pair = (2 * mt + (row >> 6)) * EE + (row & 63);
        size_t oidx = ((size_t)nt * BB * NPAIR + (size_t)b * NPAIR + pair) * 2;
        part[oidx]     = a0;
        part[oidx + 1] = a1;
    }
}

// ---------------- kernel 5: reduce 5 partials + b1 ---------------------------
__global__ void reduce_out_kernel(const float* __restrict__ part,
                                  const float* __restrict__ b1,
                                  float* __restrict__ out) {
    int i = blockIdx.x * blockDim.x + threadIdx.x;
    float a = b1[i & 1];
#pragma unroll
    for (int t = 0; t < NTILES; t++)
        a += part[(size_t)t * BB * NPAIR * 2 + i];
    out[i] = a;
}

// ---------------- launch -----------------------------------------------------
extern "C" void kernel_launch(void* const* d_in, const int* in_sizes, int n_in,
                              void* d_out, int out_size) {
    const float* piece = (const float*)d_in[0];
    const int*   widx  = (const int*)d_in[1];
    const int*   tidx  = (const int*)d_in[2];
    const int*   eidx  = (const int*)d_in[3];
    const float* W0    = (const float*)d_in[4];
    const float* b0    = (const float*)d_in[5];
    const float* W1    = (const float*)d_in[6];
    const float* b1    = (const float*)d_in[7];
    float* out = (float*)d_out;

    float *wordp, *trigp, *entp, *ptp, *pep, *partp;
    __half* w0tp;
    cudaGetSymbolAddress((void**)&wordp, g_word);
    cudaGetSymbolAddress((void**)&trigp, g_trig);
    cudaGetSymbolAddress((void**)&entp,  g_ent);
    cudaGetSymbolAddress((void**)&w0tp,  g_W0T);
    cudaGetSymbolAddress((void**)&ptp,   g_Pt);
    cudaGetSymbolAddress((void**)&pep,   g_Pe);
    cudaGetSymbolAddress((void**)&partp, g_part);

    cudaFuncSetAttribute(pair_mma_kernel,
                         cudaFuncAttributeMaxDynamicSharedMemorySize, SMEM_DYN);

    word_mean_kernel<<<dim3(WW, BB), 256>>>(piece, widx, wordp);
    span_mean_kernel<<<dim3(TT, BB), 256>>>(wordp, tidx, trigp, TT);
    span_mean_kernel<<<dim3(EE, BB), 256>>>(wordp, eidx, entp, EE);
    bprep_kernel<<<dim3(KF / 32, NPAD / 32), dim3(32, 32)>>>(W0, w0tp);
    pgemm_kernel<<<dim3(NTILES, (BB * TT) / 128), 256>>>(trigp, w0tp, 0, b0, ptp);
    pgemm_kernel<<<dim3(NTILES, (BB * EE) / 128), 256>>>(entp, w0tp, DD, nullptr, pep);
    pair_mma_kernel<<<dim3(NTILES, TT / 2, BB), 256, SMEM_DYN>>>(
        trigp, entp, w0tp, ptp, pep, W1, partp);
    reduce_out_kernel<<<(BB * NPAIR * 2) / 1024, 1024>>>(partp, b1, out);
    (void)in_sizes; (void)n_in; (void)out_size;
}

// round 8
// speedup vs baseline: 4.7881x; 1.3363x over previous
#include <cuda_runtime.h>
#include <cuda_fp16.h>
#include <math.h>
#include <stdint.h>

// Problem constants
#define BB 16
#define PP 512
#define DD 1024
#define WW 400
#define TT 32
#define EE 64
#define HH 600
#define NPAIR (TT * EE)     // 2048
#define KF 4096             // W0T row length
#define KPOFF 2048          // pair-GEMM feature base: [t*e | |t-e|]
#define KP 2048             // pair-GEMM K
#define NPAD 640
#define KC 64               // k per chunk
#define NCHUNK 32           // KP / KC
#define NTILES 5            // h tiles of 128

// smem geometry (bytes): stage = A[128][64h] + B[128][64h], pitch 144
#define PITCH 144
#define B_OFF (128 * PITCH)               // 18432
#define STAGE_BYTES (2 * 128 * PITCH)     // 36864
#define NSTAGE 3
#define SMEM_DYN (NSTAGE * STAGE_BYTES)   // 110592

// ---------------- scratch ----------------------------------------------------
__device__ float g_word[(size_t)BB * WW * DD];
__device__ float g_trig[(size_t)BB * TT * DD];
__device__ float g_ent [(size_t)BB * EE * DD];
__device__ __half g_W0T[(size_t)NPAD * KF];            // W0^T fp16 [n][k]
__device__ __half g_A  [(size_t)BB * NPAIR * KP];      // pair features fp16 (134MB)
__device__ float g_Pt [(size_t)BB * TT * NPAD];
__device__ float g_Pe [(size_t)BB * EE * NPAD];
__device__ float g_part[(size_t)NTILES * BB * NPAIR * 2];

// ---------------- helpers ----------------------------------------------------
__device__ __forceinline__ void mma16816(float* c, const uint32_t* a, const uint32_t* b) {
    asm volatile(
        "mma.sync.aligned.m16n8k16.row.col.f32.f16.f16.f32 "
        "{%0,%1,%2,%3}, {%4,%5,%6,%7}, {%8,%9}, {%0,%1,%2,%3};"
        : "+f"(c[0]), "+f"(c[1]), "+f"(c[2]), "+f"(c[3])
        : "r"(a[0]), "r"(a[1]), "r"(a[2]), "r"(a[3]), "r"(b[0]), "r"(b[1]));
}
__device__ __forceinline__ void cp16(uint32_t dst, const void* src) {
    asm volatile("cp.async.ca.shared.global [%0], [%1], 16;" :: "r"(dst), "l"(src) : "memory");
}
__device__ __forceinline__ uint32_t smem_u32(const void* p) {
    uint32_t a;
    asm("{ .reg .u64 t; cvta.to.shared.u64 t, %1; cvt.u32.u64 %0, t; }"
        : "=r"(a) : "l"(p));
    return a;
}
__device__ __forceinline__ uint32_t pack_h2(float lo, float hi) {
    uint32_t r;
    asm("cvt.rn.f16x2.f32 %0, %1, %2;" : "=r"(r) : "f"(hi), "f"(lo));
    return r;
}

// ---------------- kernel 1: wordpiece -> word mean ---------------------------
__global__ void word_mean_kernel(const float* __restrict__ piece,
                                 const int* __restrict__ widx,
                                 float* __restrict__ out) {
    int w = blockIdx.x, b = blockIdx.y;
    int s = widx[(b * WW + w) * 2];
    int e = widx[(b * WW + w) * 2 + 1];
    float inv = 1.0f / (float)(e - s);
    const float* base = piece + (size_t)b * PP * DD;
    int t = threadIdx.x;
    float a0 = 0.f, a1 = 0.f, a2 = 0.f, a3 = 0.f;
    for (int r = s; r < e; r++) {
        float4 v = ((const float4*)(base + (size_t)r * DD))[t];
        a0 += v.x; a1 += v.y; a2 += v.z; a3 += v.w;
    }
    float4 o = make_float4(a0 * inv, a1 * inv, a2 * inv, a3 * inv);
    ((float4*)(out + (size_t)(b * WW + w) * DD))[t] = o;
}

// ---------------- kernel 2: word -> span means (trig + ent fused) ------------
__global__ void spans_kernel(const float* __restrict__ words,
                             const int* __restrict__ tidx,
                             const int* __restrict__ eidx,
                             float* __restrict__ trig,
                             float* __restrict__ ent) {
    int m = blockIdx.x, b = blockIdx.y;
    const int* idx;
    float* out;
    int mm, M;
    if (m < TT) { idx = tidx; out = trig; mm = m; M = TT; }
    else        { idx = eidx; out = ent;  mm = m - TT; M = EE; }
    int s = idx[(b * M + mm) * 2];
    int e = idx[(b * M + mm) * 2 + 1];
    float inv = 1.0f / (float)(e - s);
    const float* base = words + (size_t)b * WW * DD;
    int t = threadIdx.x;
    float a0 = 0.f, a1 = 0.f, a2 = 0.f, a3 = 0.f;
    for (int r = s; r < e; r++) {
        float4 v = ((const float4*)(base + (size_t)r * DD))[t];
        a0 += v.x; a1 += v.y; a2 += v.z; a3 += v.w;
    }
    float4 o = make_float4(a0 * inv, a1 * inv, a2 * inv, a3 * inv);
    ((float4*)(out + (size_t)(b * M + mm) * DD))[t] = o;
}

// ---------------- kernel 3: W0 [k][HH] -> W0T fp16 [NPAD][KF] ----------------
__global__ void bprep_kernel(const float* __restrict__ W0,
                             __half* __restrict__ W0T) {
    __shared__ float tile[32][33];
    int k0 = blockIdx.x * 32, n0 = blockIdx.y * 32;
    int x = threadIdx.x, y = threadIdx.y;
    float v = 0.f;
    if (n0 + x < HH) v = W0[(size_t)(k0 + y) * HH + (n0 + x)];
    tile[y][x] = v;
    __syncthreads();
    float w = tile[x][y];
    W0T[(size_t)(n0 + y) * KF + (k0 + x)] = __float2half_rn(w);
}

// ---------------- kernel 3c: A-gen: pair features fp16 -----------------------
// grid (NPAIR, BB), block 128. Row = [t*e (k<1024) | |t-e| (k>=1024)].
__global__ void agen_kernel(const float* __restrict__ trig,
                            const float* __restrict__ ent,
                            __half* __restrict__ A) {
    int pair = blockIdx.x, b = blockIdx.y;
    int t = pair >> 6, e = pair & 63;
    int tid = threadIdx.x;
    const float4* tr = (const float4*)(trig + ((size_t)b * TT + t) * DD + tid * 8);
    const float4* er = (const float4*)(ent  + ((size_t)b * EE + e) * DD + tid * 8);
    float4 t0 = tr[0], t1 = tr[1];
    float4 e0 = er[0], e1 = er[1];
    size_t rowo = ((size_t)b * NPAIR + pair) * KP;
    uint4 p;
    p.x = pack_h2(t0.x * e0.x, t0.y * e0.y);
    p.y = pack_h2(t0.z * e0.z, t0.w * e0.w);
    p.z = pack_h2(t1.x * e1.x, t1.y * e1.y);
    p.w = pack_h2(t1.z * e1.z, t1.w * e1.w);
    *(uint4*)(A + rowo + tid * 8) = p;
    uint4 d;
    d.x = pack_h2(fabsf(t0.x - e0.x), fabsf(t0.y - e0.y));
    d.y = pack_h2(fabsf(t0.z - e0.z), fabsf(t0.w - e0.w));
    d.z = pack_h2(fabsf(t1.x - e1.x), fabsf(t1.y - e1.y));
    d.w = pack_h2(fabsf(t1.z - e1.z), fabsf(t1.w - e1.w));
    *(uint4*)(A + rowo + 1024 + tid * 8) = d;
}

// ---------------- kernel 3b: combined P GEMM (Pt + Pe in one launch) ---------
// grid (NTILES, 12): mt<4 -> Pt rows (trig, koff 0, +b0); else Pe rows.
__global__ __launch_bounds__(256)
void pgemm_kernel(const float* __restrict__ trig,
                  const float* __restrict__ ent,
                  const __half* __restrict__ W0T,
                  const float* __restrict__ b0,
                  float* __restrict__ Pt,
                  float* __restrict__ Pe) {
    __shared__ char psm[STAGE_BYTES];
    uint32_t sb = smem_u32(psm);
    int tid = threadIdx.x;
    int lane = tid & 31, warp = tid >> 5;
    int wm = warp >> 2, wn = warp & 3;
    int g = lane >> 2, t2 = (lane & 3) * 2;
    int nt = blockIdx.x, mtg = blockIdx.y;
    int n0 = nt * 128;

    const float* X;
    float* C;
    const float* bias;
    int m0, koff;
    if (mtg < 4) { X = trig; C = Pt; bias = b0;      m0 = mtg * 128;       koff = 0;  }
    else         { X = ent;  C = Pe; bias = nullptr; m0 = (mtg - 4) * 128; koff = DD; }

    int prow = tid >> 1;
    int cb = (tid & 1) * 32;
    const float* xrow = X + (size_t)(m0 + prow) * DD;
    uint32_t aDst = sb + (uint32_t)prow * PITCH + cb * 2;
    uint32_t bDst = sb + B_OFF + (uint32_t)prow * PITCH + cb * 2;
    const __half* bSrcBase = W0T + (size_t)(n0 + prow) * KF + koff + cb;

    uint32_t aLd = sb + (uint32_t)(wm * 64 + g) * PITCH + (uint32_t)t2 * 2;
    uint32_t bLd = sb + B_OFF + (uint32_t)(wn * 32 + g) * PITCH + (uint32_t)t2 * 2;

    float acc[4][4][4];
#pragma unroll
    for (int i = 0; i < 4; i++)
#pragma unroll
        for (int j = 0; j < 4; j++)
#pragma unroll
            for (int q = 0; q < 4; q++) acc[i][j][q] = 0.f;

    for (int c = 0; c < DD / KC; c++) {
        float xv[32];
#pragma unroll
        for (int q = 0; q < 8; q++) {
            float4 v = ((const float4*)(xrow + c * KC + cb))[q];
            xv[q*4+0] = v.x; xv[q*4+1] = v.y; xv[q*4+2] = v.z; xv[q*4+3] = v.w;
        }
        const char* bs = (const char*)(bSrcBase + c * KC);
#pragma unroll
        for (int q = 0; q < 4; q++)
            cp16(bDst + q * 16, bs + q * 16);
#pragma unroll
        for (int gq = 0; gq < 4; gq++) {
            uint32_t p0 = pack_h2(xv[gq*8+0], xv[gq*8+1]);
            uint32_t p1 = pack_h2(xv[gq*8+2], xv[gq*8+3]);
            uint32_t p2 = pack_h2(xv[gq*8+4], xv[gq*8+5]);
            uint32_t p3 = pack_h2(xv[gq*8+6], xv[gq*8+7]);
            asm volatile("st.shared.v4.b32 [%0], {%1,%2,%3,%4};"
                         :: "r"(aDst + gq * 16), "r"(p0), "r"(p1), "r"(p2), "r"(p3) : "memory");
        }
        asm volatile("cp.async.wait_all;" ::: "memory");
        __syncthreads();
#pragma unroll
        for (int ks = 0; ks < 4; ks++) {
            uint32_t afr[4][4], bfr[4][2];
            uint32_t aO = aLd + (uint32_t)ks * 32;
            uint32_t bO = bLd + (uint32_t)ks * 32;
#pragma unroll
            for (int j = 0; j < 4; j++) {
                uint32_t o = bO + (uint32_t)j * (8 * PITCH);
                asm volatile("ld.shared.b32 %0, [%1];" : "=r"(bfr[j][0]) : "r"(o));
                asm volatile("ld.shared.b32 %0, [%1];" : "=r"(bfr[j][1]) : "r"(o + 16));
            }
#pragma unroll
            for (int i = 0; i < 4; i++) {
                uint32_t o = aO + (uint32_t)i * (16 * PITCH);
                asm volatile("ld.shared.b32 %0, [%1];" : "=r"(afr[i][0]) : "r"(o));
                asm volatile("ld.shared.b32 %0, [%1];" : "=r"(afr[i][1]) : "r"(o + 8 * PITCH));
                asm volatile("ld.shared.b32 %0, [%1];" : "=r"(afr[i][2]) : "r"(o + 16));
                asm volatile("ld.shared.b32 %0, [%1];" : "=r"(afr[i][3]) : "r"(o + 8 * PITCH + 16));
            }
#pragma unroll
            for (int i = 0; i < 4; i++)
#pragma unroll
                for (int j = 0; j < 4; j++)
                    mma16816(acc[i][j], afr[i], bfr[j]);
        }
        __syncthreads();
    }

#pragma unroll
    for (int j = 0; j < 4; j++) {
        int hcol = n0 + wn * 32 + j * 8 + t2;
#pragma unroll
        for (int cp = 0; cp < 2; cp++) {
            int h = hcol + cp;
            float bb = (bias && h < HH) ? bias[h] : 0.f;
#pragma unroll
            for (int i = 0; i < 4; i++) {
                int r0 = m0 + wm * 64 + i * 16 + g;
                C[(size_t)r0 * NPAD + h]       = acc[i][j][cp] + bb;
                C[(size_t)(r0 + 8) * NPAD + h] = acc[i][j][2 + cp] + bb;
            }
        }
    }
}

// ---------------- kernel 4: pair GEMM (pure, 3-stage cp.async) ---------------
// grid (NTILES, 256): x=nt fastest (L2 A reuse), y=mtb (b = mtb>>4, mt = mtb&15).
// 2 CTAs/SM. Epilogue: acc + Pt + Pe, relu, @W1 -> per-ntile partials.
__global__ __launch_bounds__(256, 2)
void pair_mma_kernel(const __half* __restrict__ A,
                     const __half* __restrict__ W0T,
                     const float* __restrict__ Pt,
                     const float* __restrict__ Pe,
                     const float* __restrict__ W1,
                     float* __restrict__ part) {
    extern __shared__ char dsm[];
    uint32_t sb = smem_u32(dsm);
    int tid = threadIdx.x;
    int lane = tid & 31, warp = tid >> 5;
    int wm = warp >> 2, wn = warp & 3;
    int g = lane >> 2, t2 = (lane & 3) * 2;
    int nt = blockIdx.x, mtb = blockIdx.y;
    int b = mtb >> 4, mt = mtb & 15;
    int n0 = nt * 128;

    // producer source/dst (per thread: row tid>>1, 64B segment tid&1)
    int prow = tid >> 1, pseg = tid & 1;
    const char* aSrc = (const char*)A + ((size_t)mtb * 128 + prow) * (KP * 2) + pseg * 64;
    const char* bSrc = (const char*)W0T + ((size_t)(n0 + prow) * KF + KPOFF) * 2 + pseg * 64;
    uint32_t aDst = sb + (uint32_t)prow * PITCH + pseg * 64;
    uint32_t bDst = aDst + B_OFF;

    uint32_t aLd = sb + (uint32_t)(wm * 64 + g) * PITCH + (uint32_t)t2 * 2;
    uint32_t bLd = sb + B_OFF + (uint32_t)(wn * 32 + g) * PITCH + (uint32_t)t2 * 2;

    float acc[4][4][4];
#pragma unroll
    for (int i = 0; i < 4; i++)
#pragma unroll
        for (int j = 0; j < 4; j++)
#pragma unroll
            for (int q = 0; q < 4; q++) acc[i][j][q] = 0.f;

    // prologue: issue chunks 0,1 into slots 0,1
#pragma unroll
    for (int pc = 0; pc < 2; pc++) {
        uint32_t so = (uint32_t)pc * STAGE_BYTES;
#pragma unroll
        for (int q = 0; q < 4; q++) {
            cp16(aDst + so + q * 16, aSrc + pc * 128 + q * 16);
            cp16(bDst + so + q * 16, bSrc + pc * 128 + q * 16);
        }
        asm volatile("cp.async.commit_group;" ::: "memory");
    }

    // main loop
    for (int c = 0; c < NCHUNK; c++) {
        asm volatile("cp.async.wait_group 1;" ::: "memory");
        __syncthreads();
        // issue chunk c+2 into slot (c+2)%3
        int cn = c + 2;
        if (cn < NCHUNK) {
            uint32_t so = (uint32_t)(cn % 3) * STAGE_BYTES;
#pragma unroll
            for (int q = 0; q < 4; q++) {
                cp16(aDst + so + q * 16, aSrc + cn * 128 + q * 16);
                cp16(bDst + so + q * 16, bSrc + cn * 128 + q * 16);
            }
        }
        asm volatile("cp.async.commit_group;" ::: "memory");

        uint32_t stageOff = (uint32_t)(c % 3) * STAGE_BYTES;
#pragma unroll
        for (int ks = 0; ks < 4; ks++) {
            uint32_t afr[4][4], bfr[4][2];
            uint32_t aO = aLd + stageOff + (uint32_t)ks * 32;
            uint32_t bO = bLd + stageOff + (uint32_t)ks * 32;
#pragma unroll
            for (int j = 0; j < 4; j++) {
                uint32_t o = bO + (uint32_t)j * (8 * PITCH);
                asm volatile("ld.shared.b32 %0, [%1];" : "=r"(bfr[j][0]) : "r"(o));
                asm volatile("ld.shared.b32 %0, [%1];" : "=r"(bfr[j][1]) : "r"(o + 16));
            }
#pragma unroll
            for (int i = 0; i < 4; i++) {
                uint32_t o = aO + (uint32_t)i * (16 * PITCH);
                asm volatile("ld.shared.b32 %0, [%1];" : "=r"(afr[i][0]) : "r"(o));
                asm volatile("ld.shared.b32 %0, [%1];" : "=r"(afr[i][1]) : "r"(o + 8 * PITCH));
                asm volatile("ld.shared.b32 %0, [%1];" : "=r"(afr[i][2]) : "r"(o + 16));
                asm volatile("ld.shared.b32 %0, [%1];" : "=r"(afr[i][3]) : "r"(o + 8 * PITCH + 16));
            }
#pragma unroll
            for (int i = 0; i < 4; i++)
#pragma unroll
                for (int j = 0; j < 4; j++)
                    mma16816(acc[i][j], afr[i], bfr[j]);
        }
    }
    __syncthreads();  // all smem reads done; reuse dsm for reduction

    // ---- epilogue: acc + Pt + Pe, relu, @W1 -> per-row partials
    float* red = (float*)dsm;  // [128][4][2]
    float pr[4][2][2];
#pragma unroll
    for (int i = 0; i < 4; i++)
#pragma unroll
        for (int hh = 0; hh < 2; hh++) { pr[i][hh][0] = 0.f; pr[i][hh][1] = 0.f; }

    const float* ptRow = Pt + (size_t)(b * TT + 2 * mt + wm) * NPAD;
    const float* peBase = Pe + (size_t)(b * EE) * NPAD;

#pragma unroll
    for (int j = 0; j < 4; j++) {
        int hcol = n0 + wn * 32 + j * 8 + t2;
#pragma unroll
        for (int cp = 0; cp < 2; cp++) {
            int h = hcol + cp;
            if (h < HH) {
                float pt = ptRow[h];
                float w10 = W1[2 * h], w11 = W1[2 * h + 1];
#pragma unroll
                for (int i = 0; i < 4; i++) {
                    float pe0 = peBase[(size_t)(i * 16 + g) * NPAD + h];
                    float pe1 = peBase[(size_t)(i * 16 + g + 8) * NPAD + h];
                    float v0 = fmaxf(acc[i][j][cp] + pt + pe0, 0.f);
                    float v1 = fmaxf(acc[i][j][2 + cp] + pt + pe1, 0.f);
                    pr[i][0][0] = fmaf(v0, w10, pr[i][0][0]);
                    pr[i][0][1] = fmaf(v0, w11, pr[i][0][1]);
                    pr[i][1][0] = fmaf(v1, w10, pr[i][1][0]);
                    pr[i][1][1] = fmaf(v1, w11, pr[i][1][1]);
                }
            }
        }
    }
#pragma unroll
    for (int i = 0; i < 4; i++)
#pragma unroll
        for (int hh = 0; hh < 2; hh++)
#pragma unroll
            for (int o = 0; o < 2; o++) {
                float v = pr[i][hh][o];
                v += __shfl_xor_sync(0xffffffffu, v, 1);
                v += __shfl_xor_sync(0xffffffffu, v, 2);
                pr[i][hh][o] = v;
            }
    if ((lane & 3) == 0) {
#pragma unroll
        for (int i = 0; i < 4; i++)
#pragma unroll
            for (int hh = 0; hh < 2; hh++) {
                int row = wm * 64 + i * 16 + g + hh * 8;
                red[(row * 4 + wn) * 2 + 0] = pr[i][hh][0];
                red[(row * 4 + wn) * 2 + 1] = pr[i][hh][1];
            }
    }
    __syncthreads();
    if (tid < 128) {
        int row = tid;
        float a0 = 0.f, a1 = 0.f;
#pragma unroll
        for (int wc = 0; wc < 4; wc++) {
            a0 += red[(row * 4 + wc) * 2 + 0];
            a1 += red[(row * 4 + wc) * 2 + 1];
        }
        int pair = (2 * mt + (row >> 6)) * EE + (row & 63);
        size_t oidx = ((size_t)nt * BB * NPAIR + (size_t)b * NPAIR + pair) * 2;
        part[oidx]     = a0;
        part[oidx + 1] = a1;
    }
}

// ---------------- kernel 5: reduce 5 partials + b1 ---------------------------
__global__ void reduce_out_kernel(const float* __restrict__ part,
                                  const float* __restrict__ b1,
                                  float* __restrict__ out) {
    int i = blockIdx.x * blockDim.x + threadIdx.x;
    float a = b1[i & 1];
#pragma unroll
    for (int t = 0; t < NTILES; t++)
        a += part[(size_t)t * BB * NPAIR * 2 + i];
    out[i] = a;
}

// ---------------- launch -----------------------------------------------------
extern "C" void kernel_launch(void* const* d_in, const int* in_sizes, int n_in,
                              void* d_out, int out_size) {
    const float* piece = (const float*)d_in[0];
    const int*   widx  = (const int*)d_in[1];
    const int*   tidx  = (const int*)d_in[2];
    const int*   eidx  = (const int*)d_in[3];
    const float* W0    = (const float*)d_in[4];
    const float* b0    = (const float*)d_in[5];
    const float* W1    = (const float*)d_in[6];
    const float* b1    = (const float*)d_in[7];
    float* out = (float*)d_out;

    float *wordp, *trigp, *entp, *ptp, *pep, *partp;
    __half *w0tp, *ap;
    cudaGetSymbolAddress((void**)&wordp, g_word);
    cudaGetSymbolAddress((void**)&trigp, g_trig);
    cudaGetSymbolAddress((void**)&entp,  g_ent);
    cudaGetSymbolAddress((void**)&w0tp,  g_W0T);
    cudaGetSymbolAddress((void**)&ap,    g_A);
    cudaGetSymbolAddress((void**)&ptp,   g_Pt);
    cudaGetSymbolAddress((void**)&pep,   g_Pe);
    cudaGetSymbolAddress((void**)&partp, g_part);

    cudaFuncSetAttribute(pair_mma_kernel,
                         cudaFuncAttributeMaxDynamicSharedMemorySize, SMEM_DYN);

    word_mean_kernel<<<dim3(WW, BB), 256>>>(piece, widx, wordp);
    spans_kernel<<<dim3(TT + EE, BB), 256>>>(wordp, tidx, eidx, trigp, entp);
    bprep_kernel<<<dim3(KF / 32, NPAD / 32), dim3(32, 32)>>>(W0, w0tp);
    agen_kernel<<<dim3(NPAIR, BB), 128>>>(trigp, entp, ap);
    pgemm_kernel<<<dim3(NTILES, 12), 256>>>(trigp, entp, w0tp, b0, ptp, pep);
    pair_mma_kernel<<<dim3(NTILES, 256), 256, SMEM_DYN>>>(
        ap, w0tp, ptp, pep, W1, partp);
    reduce_out_kernel<<<(BB * NPAIR * 2) / 1024, 1024>>>(partp, b1, out);
    (void)in_sizes; (void)n_in; (void)out_size;
}